// round 3
// baseline (speedup 1.0000x reference)
#include <cuda_runtime.h>
#include <math.h>

#define DIM   1024
#define BATCH 2
#define SEQ   2048
#define HEADS 16
#define HD    64
#define MROWS (BATCH*SEQ)   /* 4096 */
#define BHN   (BATCH*HEADS) /* 32 */

// ---------------- scratch (device globals: allocation-free) ----------------
__device__ float g_xn[MROWS*DIM];      // layernormed x
__device__ float g_q[BHN*SEQ*HD];      // normalized q, [bh][t][d]
__device__ float g_k[BHN*SEQ*HD];      // normalized k
__device__ float g_v[BHN*SEQ*HD];      // v pre-scaled by gate_k
__device__ float g_gateq[BHN*SEQ];
__device__ float g_coll[MROWS*DIM];    // collapse, row-major [b*T+t][h*64+d]

// ---------------- LayerNorm ----------------
__global__ void __launch_bounds__(256) ln_kernel(const float* __restrict__ x,
                                                 const float* __restrict__ w,
                                                 const float* __restrict__ b) {
    int row = blockIdx.x;
    const float4* xr = (const float4*)(x + (size_t)row * DIM);
    float4 v = xr[threadIdx.x];
    float s  = v.x + v.y + v.z + v.w;
    float ss = v.x*v.x + v.y*v.y + v.z*v.z + v.w*v.w;
    #pragma unroll
    for (int o = 16; o > 0; o >>= 1) {
        s  += __shfl_xor_sync(0xffffffffu, s,  o);
        ss += __shfl_xor_sync(0xffffffffu, ss, o);
    }
    __shared__ float rs[8], rss[8];
    int wid = threadIdx.x >> 5, lane = threadIdx.x & 31;
    if (lane == 0) { rs[wid] = s; rss[wid] = ss; }
    __syncthreads();
    if (wid == 0) {
        float a = (lane < 8) ? rs[lane]  : 0.f;
        float c = (lane < 8) ? rss[lane] : 0.f;
        #pragma unroll
        for (int o = 4; o > 0; o >>= 1) {
            a += __shfl_xor_sync(0xffffffffu, a, o);
            c += __shfl_xor_sync(0xffffffffu, c, o);
        }
        if (lane == 0) { rs[0] = a; rss[0] = c; }
    }
    __syncthreads();
    float mu   = rs[0] * (1.0f / DIM);
    float var  = rss[0] * (1.0f / DIM) - mu * mu;
    float rstd = rsqrtf(var + 1e-5f);
    int c0 = threadIdx.x * 4;
    float4 wv = *(const float4*)(w + c0);
    float4 bv = *(const float4*)(b + c0);
    float4 y;
    y.x = (v.x - mu) * rstd * wv.x + bv.x;
    y.y = (v.y - mu) * rstd * wv.y + bv.y;
    y.z = (v.z - mu) * rstd * wv.z + bv.z;
    y.w = (v.w - mu) * rstd * wv.w + bv.w;
    *(float4*)(g_xn + (size_t)row * DIM + c0) = y;
}

// ---------------- QKV projection GEMM (128x128x8, 8x8 microtile) ----------------
// C[r][c] = sum_k A[r][k] * W[k][c], stored in [B,H,T,HD] head layout.
__global__ void __launch_bounds__(256) gemm_qkv(const float* __restrict__ x,
                                                const float* __restrict__ Wq,
                                                const float* __restrict__ Wk,
                                                const float* __restrict__ Wv) {
    int mode = blockIdx.z;
    const float* A = (mode == 2) ? x : g_xn;
    const float* W = (mode == 0) ? Wq : ((mode == 1) ? Wk : Wv);
    float* C = (mode == 0) ? g_q : ((mode == 1) ? g_k : g_v);

    __shared__ float sA[8][128];
    __shared__ float sB[8][128];
    int tid = threadIdx.x;
    int tx = tid & 15, ty = tid >> 4;
    int row0 = blockIdx.y * 128, col0 = blockIdx.x * 128;

    int aRow = tid >> 1, aK = (tid & 1) * 4;
    int bK   = tid >> 5, bCol = (tid & 31) * 4;

    float acc[8][8];
    #pragma unroll
    for (int i = 0; i < 8; i++)
        #pragma unroll
        for (int j = 0; j < 8; j++) acc[i][j] = 0.f;

    const float* Aptr = A + (size_t)(row0 + aRow) * DIM + aK;
    const float* Wptr = W + (size_t)bK * DIM + col0 + bCol;

    for (int k0 = 0; k0 < DIM; k0 += 8) {
        float4 av = *(const float4*)(Aptr + k0);
        float4 bv = *(const float4*)(Wptr + (size_t)k0 * DIM);
        sA[aK + 0][aRow] = av.x;
        sA[aK + 1][aRow] = av.y;
        sA[aK + 2][aRow] = av.z;
        sA[aK + 3][aRow] = av.w;
        *(float4*)&sB[bK][bCol] = bv;
        __syncthreads();
        #pragma unroll
        for (int kk = 0; kk < 8; kk++) {
            float a[8], bb[8];
            *(float4*)&a[0]  = *(float4*)&sA[kk][ty * 8];
            *(float4*)&a[4]  = *(float4*)&sA[kk][ty * 8 + 4];
            *(float4*)&bb[0] = *(float4*)&sB[kk][tx * 8];
            *(float4*)&bb[4] = *(float4*)&sB[kk][tx * 8 + 4];
            #pragma unroll
            for (int i = 0; i < 8; i++)
                #pragma unroll
                for (int j = 0; j < 8; j++)
                    acc[i][j] = fmaf(a[i], bb[j], acc[i][j]);
        }
        __syncthreads();
    }

    // epilogue: head layout [ (b*H+h)*SEQ + t ][ d ]
    #pragma unroll
    for (int i = 0; i < 8; i++) {
        int r = row0 + ty * 8 + i;
        int bb_ = r >> 11, t = r & 2047;
        #pragma unroll
        for (int jv = 0; jv < 2; jv++) {
            int c = col0 + tx * 8 + jv * 4;
            int h = c >> 6, d = c & 63;
            float4 o = make_float4(acc[i][jv*4+0], acc[i][jv*4+1], acc[i][jv*4+2], acc[i][jv*4+3]);
            *(float4*)&C[((size_t)(bb_ * HEADS + h) * SEQ + t) * HD + d] = o;
        }
    }
}

// ---------------- per-head l2 normalize + gates ----------------
// isK==0: normalize q rows in place, store gate_q = qn . gq
// isK==1: normalize k rows in place, scale matching v row by gate_k = kn . gk
__global__ void __launch_bounds__(256) headnorm_kernel(int isK, const float* __restrict__ g) {
    int row  = (blockIdx.x << 3) + (threadIdx.x >> 5);  // one warp per row
    int lane = threadIdx.x & 31;
    float* base = (isK ? g_k : g_q) + (size_t)row * HD;
    float v0 = base[lane], v1 = base[lane + 32];
    float ss = v0 * v0 + v1 * v1;
    #pragma unroll
    for (int o = 16; o > 0; o >>= 1) ss += __shfl_xor_sync(0xffffffffu, ss, o);
    float n = sqrtf(ss);
    float r = 1.0f / fmaxf(n, 1e-12f);
    v0 *= r; v1 *= r;
    base[lane] = v0; base[lane + 32] = v1;
    float gt = v0 * g[lane] + v1 * g[lane + 32];
    #pragma unroll
    for (int o = 16; o > 0; o >>= 1) gt += __shfl_xor_sync(0xffffffffu, gt, o);
    if (isK) {
        float* vb = g_v + (size_t)row * HD;
        vb[lane] *= gt;
        vb[lane + 32] *= gt;
    } else if (lane == 0) {
        g_gateq[row] = gt;
    }
}

// ---------------- attention: O = sigmoid((Q K^T - th)*sharp) @ V' , * gate_q ----------------
// 64x64 q-tile per block, loop over 32 s-tiles, 4x4 microtile, 256 threads.
#define AP 68  // smem pitch (floats), 16B aligned, breaks worst bank conflicts
__global__ void __launch_bounds__(256) attn_kernel() {
    extern __shared__ float sm[];
    float* sQ  = sm;             // [d][m], pitch AP  (transposed q tile)
    float* sKP = sm + 64 * AP;   // phase1: [d][n] kT ; phase2: [s][m] P^T
    float* sV  = sm + 128 * AP;  // [s][d]

    int bh = blockIdx.y;
    int t0 = blockIdx.x * 64;
    const float* Q = g_q + ((size_t)bh * SEQ + t0) * HD;
    const float* K = g_k + (size_t)bh * SEQ * HD;
    const float* V = g_v + (size_t)bh * SEQ * HD;

    int tid = threadIdx.x, tx = tid & 15, ty = tid >> 4;

    for (int e = tid; e < 4096; e += 256) {
        int t = e >> 6, d = e & 63;
        sQ[d * AP + t] = Q[t * HD + d];
    }

    float O[4][4];
    #pragma unroll
    for (int i = 0; i < 4; i++)
        #pragma unroll
        for (int j = 0; j < 4; j++) O[i][j] = 0.f;

    for (int s0 = 0; s0 < SEQ; s0 += 64) {
        __syncthreads();  // covers sQ load (iter 0) and prior-iter sKP/sV reads
        const float* Kt = K + (size_t)s0 * HD;
        const float* Vt = V + (size_t)s0 * HD;
        for (int e = tid; e < 4096; e += 256) {
            int s = e >> 6, d = e & 63;
            sKP[d * AP + s] = Kt[s * HD + d];
            sV[s * AP + d]  = Vt[s * HD + d];
        }
        __syncthreads();

        float S[4][4];
        #pragma unroll
        for (int i = 0; i < 4; i++)
            #pragma unroll
            for (int j = 0; j < 4; j++) S[i][j] = 0.f;

        #pragma unroll 16
        for (int kk = 0; kk < 64; kk++) {
            float4 a = *(float4*)&sQ[kk * AP + ty * 4];
            float4 b = *(float4*)&sKP[kk * AP + tx * 4];
            float av[4] = {a.x, a.y, a.z, a.w};
            float bv[4] = {b.x, b.y, b.z, b.w};
            #pragma unroll
            for (int i = 0; i < 4; i++)
                #pragma unroll
                for (int j = 0; j < 4; j++)
                    S[i][j] = fmaf(av[i], bv[j], S[i][j]);
        }

        float Pm[4][4];
        #pragma unroll
        for (int i = 0; i < 4; i++)
            #pragma unroll
            for (int j = 0; j < 4; j++) {
                float z = (S[i][j] - 0.29514f) * 15.0f;
                Pm[i][j] = 1.0f / (1.0f + __expf(-z));
            }

        __syncthreads();  // everyone done reading sKP (k tile)
        #pragma unroll
        for (int j = 0; j < 4; j++) {
            float4 pv = make_float4(Pm[0][j], Pm[1][j], Pm[2][j], Pm[3][j]);
            *(float4*)&sKP[(tx * 4 + j) * AP + ty * 4] = pv;  // P^T: [s][m]
        }
        __syncthreads();

        #pragma unroll 16
        for (int s = 0; s < 64; s++) {
            float4 a = *(float4*)&sKP[s * AP + ty * 4];  // P^T row
            float4 b = *(float4*)&sV[s * AP + tx * 4];   // V row
            float av[4] = {a.x, a.y, a.z, a.w};
            float bv[4] = {b.x, b.y, b.z, b.w};
            #pragma unroll
            for (int i = 0; i < 4; i++)
                #pragma unroll
                for (int j = 0; j < 4; j++)
                    O[i][j] = fmaf(av[i], bv[j], O[i][j]);
        }
    }

    int b = bh >> 4, h = bh & 15;
    #pragma unroll
    for (int i = 0; i < 4; i++) {
        int t = t0 + ty * 4 + i;
        float gqv = g_gateq[(size_t)bh * SEQ + t];
        float4 o = make_float4(O[i][0] * gqv, O[i][1] * gqv, O[i][2] * gqv, O[i][3] * gqv);
        *(float4*)&g_coll[((size_t)(b * SEQ + t) * HEADS + h) * HD + tx * 4] = o;
    }
}

// ---------------- output GEMM + bias ----------------
__global__ void __launch_bounds__(256) gemm_out(const float* __restrict__ Wo,
                                                const float* __restrict__ bo,
                                                float* __restrict__ out) {
    __shared__ float sA[8][128];
    __shared__ float sB[8][128];
    int tid = threadIdx.x;
    int tx = tid & 15, ty = tid >> 4;
    int row0 = blockIdx.y * 128, col0 = blockIdx.x * 128;

    int aRow = tid >> 1, aK = (tid & 1) * 4;
    int bK   = tid >> 5, bCol = (tid & 31) * 4;

    float acc[8][8];
    #pragma unroll
    for (int i = 0; i < 8; i++)
        #pragma unroll
        for (int j = 0; j < 8; j++) acc[i][j] = 0.f;

    const float* Aptr = g_coll + (size_t)(row0 + aRow) * DIM + aK;
    const float* Wptr = Wo + (size_t)bK * DIM + col0 + bCol;

    for (int k0 = 0; k0 < DIM; k0 += 8) {
        float4 av = *(const float4*)(Aptr + k0);
        float4 bv = *(const float4*)(Wptr + (size_t)k0 * DIM);
        sA[aK + 0][aRow] = av.x;
        sA[aK + 1][aRow] = av.y;
        sA[aK + 2][aRow] = av.z;
        sA[aK + 3][aRow] = av.w;
        *(float4*)&sB[bK][bCol] = bv;
        __syncthreads();
        #pragma unroll
        for (int kk = 0; kk < 8; kk++) {
            float a[8], bb[8];
            *(float4*)&a[0]  = *(float4*)&sA[kk][ty * 8];
            *(float4*)&a[4]  = *(float4*)&sA[kk][ty * 8 + 4];
            *(float4*)&bb[0] = *(float4*)&sB[kk][tx * 8];
            *(float4*)&bb[4] = *(float4*)&sB[kk][tx * 8 + 4];
            #pragma unroll
            for (int i = 0; i < 8; i++)
                #pragma unroll
                for (int j = 0; j < 8; j++)
                    acc[i][j] = fmaf(a[i], bb[j], acc[i][j]);
        }
        __syncthreads();
    }

    #pragma unroll
    for (int i = 0; i < 8; i++) {
        int r = row0 + ty * 8 + i;
        #pragma unroll
        for (int jv = 0; jv < 2; jv++) {
            int c = col0 + tx * 8 + jv * 4;
            float4 bv = *(const float4*)(bo + c);
            float4 o = make_float4(acc[i][jv*4+0] + bv.x, acc[i][jv*4+1] + bv.y,
                                   acc[i][jv*4+2] + bv.z, acc[i][jv*4+3] + bv.w);
            *(float4*)&out[(size_t)r * DIM + c] = o;
        }
    }
}

// ---------------- launcher ----------------
extern "C" void kernel_launch(void* const* d_in, const int* in_sizes, int n_in,
                              void* d_out, int out_size) {
    const float* x   = (const float*)d_in[0];
    const float* Wq  = (const float*)d_in[1];
    const float* Wk  = (const float*)d_in[2];
    const float* Wv  = (const float*)d_in[3];
    const float* gq  = (const float*)d_in[4];
    const float* gk  = (const float*)d_in[5];
    const float* Wo  = (const float*)d_in[6];
    const float* bo  = (const float*)d_in[7];
    const float* lnw = (const float*)d_in[8];
    const float* lnb = (const float*)d_in[9];
    float* out = (float*)d_out;

    // attn needs 3*64*68*4 = 52224 B dynamic smem (> 48K default).
    // Not a stream op; safe under graph capture, idempotent.
    cudaFuncSetAttribute(attn_kernel, cudaFuncAttributeMaxDynamicSharedMemorySize, 3 * 64 * AP * 4);

    ln_kernel<<<MROWS, 256>>>(x, lnw, lnb);
    gemm_qkv<<<dim3(8, 32, 3), 256>>>(x, Wq, Wk, Wv);
    headnorm_kernel<<<(BHN * SEQ) / 8, 256>>>(0, gq);
    headnorm_kernel<<<(BHN * SEQ) / 8, 256>>>(1, gk);
    attn_kernel<<<dim3(SEQ / 64, BHN), 256, 3 * 64 * AP * 4>>>();
    gemm_out<<<dim3(8, 32), 256>>>(Wo, bo, out);
}

// round 7
// speedup vs baseline: 2.3351x; 2.3351x over previous
#include <cuda_runtime.h>
#include <math.h>
#include <stdint.h>

#define DIM   1024
#define BATCH 2
#define SEQ   2048
#define HEADS 16
#define HD    64
#define MROWS (BATCH*SEQ)   /* 4096 */
#define BHN   (BATCH*HEADS) /* 32 */

// ---------------- scratch (device globals: allocation-free) ----------------
__device__ float g_xn[MROWS*DIM];      // layernormed x
__device__ float g_q[BHN*SEQ*HD];      // normalized q, [bh][t][d]
__device__ float g_k[BHN*SEQ*HD];      // normalized k
__device__ float g_v[BHN*SEQ*HD];      // v pre-scaled by gate_k
__device__ float g_gateq[BHN*SEQ];
__device__ float g_coll[MROWS*DIM];    // collapse, row-major [b*T+t][h*64+d]

// ---------------- tf32 helpers ----------------
__device__ __forceinline__ uint32_t f2tf(float x) {
    uint32_t u;
    asm("cvt.rna.tf32.f32 %0, %1;" : "=r"(u) : "f"(x));
    return u;
}

// D += A(16x8,row) * B(8x8,col), tf32 inputs, fp32 accum
__device__ __forceinline__ void mma8(float c[4],
                                     uint32_t a0, uint32_t a1, uint32_t a2, uint32_t a3,
                                     uint32_t b0, uint32_t b1) {
    asm volatile(
        "mma.sync.aligned.m16n8k8.row.col.f32.tf32.tf32.f32 "
        "{%0,%1,%2,%3},{%4,%5,%6,%7},{%8,%9},{%0,%1,%2,%3};"
        : "+f"(c[0]), "+f"(c[1]), "+f"(c[2]), "+f"(c[3])
        : "r"(a0), "r"(a1), "r"(a2), "r"(a3), "r"(b0), "r"(b1));
}

// ---------------- LayerNorm ----------------
__global__ void __launch_bounds__(256) ln_kernel(const float* __restrict__ x,
                                                 const float* __restrict__ w,
                                                 const float* __restrict__ b) {
    int row = blockIdx.x;
    const float4* xr = (const float4*)(x + (size_t)row * DIM);
    float4 v = xr[threadIdx.x];
    float s  = v.x + v.y + v.z + v.w;
    float ss = v.x*v.x + v.y*v.y + v.z*v.z + v.w*v.w;
    #pragma unroll
    for (int o = 16; o > 0; o >>= 1) {
        s  += __shfl_xor_sync(0xffffffffu, s,  o);
        ss += __shfl_xor_sync(0xffffffffu, ss, o);
    }
    __shared__ float rs[8], rss[8];
    int wid = threadIdx.x >> 5, lane = threadIdx.x & 31;
    if (lane == 0) { rs[wid] = s; rss[wid] = ss; }
    __syncthreads();
    if (wid == 0) {
        float a = (lane < 8) ? rs[lane]  : 0.f;
        float c = (lane < 8) ? rss[lane] : 0.f;
        #pragma unroll
        for (int o = 4; o > 0; o >>= 1) {
            a += __shfl_xor_sync(0xffffffffu, a, o);
            c += __shfl_xor_sync(0xffffffffu, c, o);
        }
        if (lane == 0) { rs[0] = a; rss[0] = c; }
    }
    __syncthreads();
    float mu   = rs[0] * (1.0f / DIM);
    float var  = rss[0] * (1.0f / DIM) - mu * mu;
    float rstd = rsqrtf(var + 1e-5f);
    int c0 = threadIdx.x * 4;
    float4 wv = *(const float4*)(w + c0);
    float4 bv = *(const float4*)(b + c0);
    float4 y;
    y.x = (v.x - mu) * rstd * wv.x + bv.x;
    y.y = (v.y - mu) * rstd * wv.y + bv.y;
    y.z = (v.z - mu) * rstd * wv.z + bv.z;
    y.w = (v.w - mu) * rstd * wv.w + bv.w;
    *(float4*)(g_xn + (size_t)row * DIM + c0) = y;
}

// ---------------- QKV projection GEMM (tf32 mma, 128x128x16) ----------------
#define GPA 20    // sA pitch: [m][k], 16+4 -> bank(4g+... ) conflict-free frag reads
#define GPB 136   // sB pitch: [k][n], 128+8 -> bank(8tg+g) conflict-free frag reads
__global__ void __launch_bounds__(256) gemm_qkv(const float* __restrict__ x,
                                                const float* __restrict__ Wq,
                                                const float* __restrict__ Wk,
                                                const float* __restrict__ Wv) {
    int mode = blockIdx.z;
    const float* A = (mode == 2) ? x : g_xn;
    const float* W = (mode == 0) ? Wq : ((mode == 1) ? Wk : Wv);
    float* C = (mode == 0) ? g_q : ((mode == 1) ? g_k : g_v);

    __shared__ uint32_t sA[128 * GPA];
    __shared__ uint32_t sB[16 * GPB];

    int tid = threadIdx.x, lane = tid & 31, wid = tid >> 5;
    int g = lane >> 2, tg = lane & 3;
    int m0  = (wid & 3) * 32;      // warp row origin within block
    int n0b = (wid >> 2) * 64;     // warp col origin within block
    int row0 = blockIdx.y * 128, col0 = blockIdx.x * 128;

    int aRow = tid >> 1, aOff = (tid & 1) * 8;
    int bK = tid >> 4, bN = (tid & 15) * 8;

    float acc[2][8][4];
    #pragma unroll
    for (int mt = 0; mt < 2; mt++)
        #pragma unroll
        for (int nt = 0; nt < 8; nt++)
            #pragma unroll
            for (int i = 0; i < 4; i++) acc[mt][nt][i] = 0.f;

    const float* Ap = A + (size_t)(row0 + aRow) * DIM + aOff;
    const float* Wp = W + (size_t)bK * DIM + col0 + bN;

    for (int k0 = 0; k0 < DIM; k0 += 16) {
        float4 av0 = *(const float4*)(Ap + k0);
        float4 av1 = *(const float4*)(Ap + k0 + 4);
        float4 bv0 = *(const float4*)(Wp + (size_t)k0 * DIM);
        float4 bv1 = *(const float4*)(Wp + (size_t)k0 * DIM + 4);
        __syncthreads();
        uint32_t* pa = &sA[aRow * GPA + aOff];
        pa[0] = f2tf(av0.x); pa[1] = f2tf(av0.y); pa[2] = f2tf(av0.z); pa[3] = f2tf(av0.w);
        pa[4] = f2tf(av1.x); pa[5] = f2tf(av1.y); pa[6] = f2tf(av1.z); pa[7] = f2tf(av1.w);
        uint4 ub0 = make_uint4(f2tf(bv0.x), f2tf(bv0.y), f2tf(bv0.z), f2tf(bv0.w));
        uint4 ub1 = make_uint4(f2tf(bv1.x), f2tf(bv1.y), f2tf(bv1.z), f2tf(bv1.w));
        *(uint4*)&sB[bK * GPB + bN]     = ub0;
        *(uint4*)&sB[bK * GPB + bN + 4] = ub1;
        __syncthreads();

        #pragma unroll
        for (int ks = 0; ks < 2; ks++) {
            int kk = ks * 8;
            uint32_t aF[2][4];
            #pragma unroll
            for (int mt = 0; mt < 2; mt++) {
                int mr = m0 + mt * 16;
                aF[mt][0] = sA[(mr + g)     * GPA + kk + tg];
                aF[mt][1] = sA[(mr + 8 + g) * GPA + kk + tg];
                aF[mt][2] = sA[(mr + g)     * GPA + kk + tg + 4];
                aF[mt][3] = sA[(mr + 8 + g) * GPA + kk + tg + 4];
            }
            uint32_t bF[8][2];
            #pragma unroll
            for (int nt = 0; nt < 8; nt++) {
                int n = n0b + nt * 8 + g;
                bF[nt][0] = sB[(kk + tg)     * GPB + n];
                bF[nt][1] = sB[(kk + tg + 4) * GPB + n];
            }
            #pragma unroll
            for (int mt = 0; mt < 2; mt++)
                #pragma unroll
                for (int nt = 0; nt < 8; nt++)
                    mma8(acc[mt][nt], aF[mt][0], aF[mt][1], aF[mt][2], aF[mt][3],
                         bF[nt][0], bF[nt][1]);
        }
    }

    // epilogue: scatter into head layout [ (b*H+h)*SEQ + t ][ d ]
    #pragma unroll
    for (int mt = 0; mt < 2; mt++) {
        int r1 = row0 + m0 + mt * 16 + g;
        int r2 = r1 + 8;
        int b1 = r1 >> 11, t1 = r1 & 2047;
        int b2 = r2 >> 11, t2 = r2 & 2047;
        #pragma unroll
        for (int nt = 0; nt < 8; nt++) {
            int c = col0 + n0b + nt * 8 + 2 * tg;
            int h = c >> 6, d = c & 63;
            *(float2*)&C[((size_t)(b1 * HEADS + h) * SEQ + t1) * HD + d] =
                make_float2(acc[mt][nt][0], acc[mt][nt][1]);
            *(float2*)&C[((size_t)(b2 * HEADS + h) * SEQ + t2) * HD + d] =
                make_float2(acc[mt][nt][2], acc[mt][nt][3]);
        }
    }
}

// ---------------- per-head l2 normalize + gates ----------------
__global__ void __launch_bounds__(256) headnorm_kernel(int isK, const float* __restrict__ g) {
    int row  = (blockIdx.x << 3) + (threadIdx.x >> 5);  // one warp per row
    int lane = threadIdx.x & 31;
    float* base = (isK ? g_k : g_q) + (size_t)row * HD;
    float v0 = base[lane], v1 = base[lane + 32];
    float ss = v0 * v0 + v1 * v1;
    #pragma unroll
    for (int o = 16; o > 0; o >>= 1) ss += __shfl_xor_sync(0xffffffffu, ss, o);
    float n = sqrtf(ss);
    float r = 1.0f / fmaxf(n, 1e-12f);
    v0 *= r; v1 *= r;
    base[lane] = v0; base[lane + 32] = v1;
    float gt = v0 * g[lane] + v1 * g[lane + 32];
    #pragma unroll
    for (int o = 16; o > 0; o >>= 1) gt += __shfl_xor_sync(0xffffffffu, gt, o);
    if (isK) {
        float* vb = g_v + (size_t)row * HD;
        vb[lane] *= gt;
        vb[lane + 32] *= gt;
    } else if (lane == 0) {
        g_gateq[row] = gt;
    }
}

// ---------------- attention (tf32 mma): O = sigmoid((QK^T-th)*sharp) @ V', *gate_q ----
// 64 q-rows x 64 s-cols per CTA, 8 warps (4x2), warp tile 16x32.
// All smem buffers pitch 68 -> frag-load bank = (4g+tg) mod 32 : conflict-free.
#define AP 68
__global__ void __launch_bounds__(256) attn_kernel() {
    extern __shared__ uint32_t sm[];
    uint32_t* sQ  = sm;               // [t(64)][d] pitch AP
    uint32_t* sK  = sm + 64 * AP;     // [s(64)][d] pitch AP
    uint32_t* sVT = sm + 128 * AP;    // [d(64)][s] pitch AP (transposed V)
    uint32_t* sP  = sm + 192 * AP;    // [t(64)][s] pitch AP (tf32 P)

    int bh = blockIdx.y;
    int t0 = blockIdx.x * 64;
    const float* Q = g_q + ((size_t)bh * SEQ + t0) * HD;
    const float* K = g_k + (size_t)bh * SEQ * HD;
    const float* V = g_v + (size_t)bh * SEQ * HD;

    int tid = threadIdx.x, lane = tid & 31, wid = tid >> 5;
    int g = lane >> 2, tg = lane & 3;
    int m0 = (wid & 3) * 16;    // warp q-row origin
    int n0 = (wid >> 2) * 32;   // warp col origin (s in phase 1, d in phase 2)

    // load Q tile (64x64), convert to tf32
    #pragma unroll
    for (int f = 0; f < 4; f++) {
        int e = tid + f * 256;
        int r = e >> 4, o = (e & 15) * 4;
        float4 v = *(const float4*)(Q + r * HD + o);
        *(uint4*)&sQ[r * AP + o] = make_uint4(f2tf(v.x), f2tf(v.y), f2tf(v.z), f2tf(v.w));
    }

    float O[4][4];
    #pragma unroll
    for (int nt = 0; nt < 4; nt++)
        #pragma unroll
        for (int i = 0; i < 4; i++) O[nt][i] = 0.f;

    for (int s0 = 0; s0 < SEQ; s0 += 64) {
        __syncthreads();  // prev-iter reads done (also covers sQ stores on iter 0 w/ next sync)
        #pragma unroll
        for (int f = 0; f < 4; f++) {
            int e = tid + f * 256;
            int r = e >> 4, o = (e & 15) * 4;
            float4 kv = *(const float4*)(K + (size_t)(s0 + r) * HD + o);
            *(uint4*)&sK[r * AP + o] = make_uint4(f2tf(kv.x), f2tf(kv.y), f2tf(kv.z), f2tf(kv.w));
            float4 vv = *(const float4*)(V + (size_t)(s0 + r) * HD + o);
            sVT[(o + 0) * AP + r] = f2tf(vv.x);
            sVT[(o + 1) * AP + r] = f2tf(vv.y);
            sVT[(o + 2) * AP + r] = f2tf(vv.z);
            sVT[(o + 3) * AP + r] = f2tf(vv.w);
        }
        __syncthreads();

        // S = Q @ K^T  (warp tile 16x32)
        float S[4][4];
        #pragma unroll
        for (int nt = 0; nt < 4; nt++)
            #pragma unroll
            for (int i = 0; i < 4; i++) S[nt][i] = 0.f;

        #pragma unroll
        for (int ks = 0; ks < 8; ks++) {
            int kk = ks * 8;
            uint32_t a0 = sQ[(m0 + g)     * AP + kk + tg];
            uint32_t a1 = sQ[(m0 + 8 + g) * AP + kk + tg];
            uint32_t a2 = sQ[(m0 + g)     * AP + kk + tg + 4];
            uint32_t a3 = sQ[(m0 + 8 + g) * AP + kk + tg + 4];
            #pragma unroll
            for (int nt = 0; nt < 4; nt++) {
                int n = n0 + nt * 8 + g;
                uint32_t b0 = sK[n * AP + kk + tg];
                uint32_t b1 = sK[n * AP + kk + tg + 4];
                mma8(S[nt], a0, a1, a2, a3, b0, b1);
            }
        }

        // sigmoid, write P (tf32) in A-operand layout [t][s]
        #pragma unroll
        for (int nt = 0; nt < 4; nt++) {
            int c = n0 + nt * 8 + 2 * tg;
            float p0 = 1.0f / (1.0f + __expf(-(S[nt][0] - 0.29514f) * 15.0f));
            float p1 = 1.0f / (1.0f + __expf(-(S[nt][1] - 0.29514f) * 15.0f));
            float p2 = 1.0f / (1.0f + __expf(-(S[nt][2] - 0.29514f) * 15.0f));
            float p3 = 1.0f / (1.0f + __expf(-(S[nt][3] - 0.29514f) * 15.0f));
            sP[(m0 + g)     * AP + c]     = f2tf(p0);
            sP[(m0 + g)     * AP + c + 1] = f2tf(p1);
            sP[(m0 + 8 + g) * AP + c]     = f2tf(p2);
            sP[(m0 + 8 + g) * AP + c + 1] = f2tf(p3);
        }
        __syncthreads();

        // O += P @ V'   (A = sP [t][s], B = sVT [d][s] as col-major 8x8)
        #pragma unroll
        for (int ks = 0; ks < 8; ks++) {
            int kk = ks * 8;
            uint32_t a0 = sP[(m0 + g)     * AP + kk + tg];
            uint32_t a1 = sP[(m0 + 8 + g) * AP + kk + tg];
            uint32_t a2 = sP[(m0 + g)     * AP + kk + tg + 4];
            uint32_t a3 = sP[(m0 + 8 + g) * AP + kk + tg + 4];
            #pragma unroll
            for (int nt = 0; nt < 4; nt++) {
                int n = n0 + nt * 8 + g;   // output d index
                uint32_t b0 = sVT[n * AP + kk + tg];
                uint32_t b1 = sVT[n * AP + kk + tg + 4];
                mma8(O[nt], a0, a1, a2, a3, b0, b1);
            }
        }
    }

    // epilogue: * gate_q, scatter to row-major collapse layout
    int b = bh >> 4, h = bh & 15;
    int t1 = t0 + m0 + g, t2 = t1 + 8;
    float gq1 = g_gateq[(size_t)bh * SEQ + t1];
    float gq2 = g_gateq[(size_t)bh * SEQ + t2];
    #pragma unroll
    for (int nt = 0; nt < 4; nt++) {
        int d = n0 + nt * 8 + 2 * tg;
        *(float2*)&g_coll[((size_t)(b * SEQ + t1) * HEADS + h) * HD + d] =
            make_float2(O[nt][0] * gq1, O[nt][1] * gq1);
        *(float2*)&g_coll[((size_t)(b * SEQ + t2) * HEADS + h) * HD + d] =
            make_float2(O[nt][2] * gq2, O[nt][3] * gq2);
    }
}

// ---------------- output GEMM + bias (tf32 mma) ----------------
__global__ void __launch_bounds__(256) gemm_out(const float* __restrict__ Wo,
                                                const float* __restrict__ bo,
                                                float* __restrict__ out) {
    __shared__ uint32_t sA[128 * GPA];
    __shared__ uint32_t sB[16 * GPB];

    int tid = threadIdx.x, lane = tid & 31, wid = tid >> 5;
    int g = lane >> 2, tg = lane & 3;
    int m0  = (wid & 3) * 32;
    int n0b = (wid >> 2) * 64;
    int row0 = blockIdx.y * 128, col0 = blockIdx.x * 128;

    int aRow = tid >> 1, aOff = (tid & 1) * 8;
    int bK = tid >> 4, bN = (tid & 15) * 8;

    float acc[2][8][4];
    #pragma unroll
    for (int mt = 0; mt < 2; mt++)
        #pragma unroll
        for (int nt = 0; nt < 8; nt++)
            #pragma unroll
            for (int i = 0; i < 4; i++) acc[mt][nt][i] = 0.f;

    const float* Ap = g_coll + (size_t)(row0 + aRow) * DIM + aOff;
    const float* Wp = Wo + (size_t)bK * DIM + col0 + bN;

    for (int k0 = 0; k0 < DIM; k0 += 16) {
        float4 av0 = *(const float4*)(Ap + k0);
        float4 av1 = *(const float4*)(Ap + k0 + 4);
        float4 bv0 = *(const float4*)(Wp + (size_t)k0 * DIM);
        float4 bv1 = *(const float4*)(Wp + (size_t)k0 * DIM + 4);
        __syncthreads();
        uint32_t* pa = &sA[aRow * GPA + aOff];
        pa[0] = f2tf(av0.x); pa[1] = f2tf(av0.y); pa[2] = f2tf(av0.z); pa[3] = f2tf(av0.w);
        pa[4] = f2tf(av1.x); pa[5] = f2tf(av1.y); pa[6] = f2tf(av1.z); pa[7] = f2tf(av1.w);
        *(uint4*)&sB[bK * GPB + bN]     = make_uint4(f2tf(bv0.x), f2tf(bv0.y), f2tf(bv0.z), f2tf(bv0.w));
        *(uint4*)&sB[bK * GPB + bN + 4] = make_uint4(f2tf(bv1.x), f2tf(bv1.y), f2tf(bv1.z), f2tf(bv1.w));
        __syncthreads();

        #pragma unroll
        for (int ks = 0; ks < 2; ks++) {
            int kk = ks * 8;
            uint32_t aF[2][4];
            #pragma unroll
            for (int mt = 0; mt < 2; mt++) {
                int mr = m0 + mt * 16;
                aF[mt][0] = sA[(mr + g)     * GPA + kk + tg];
                aF[mt][1] = sA[(mr + 8 + g) * GPA + kk + tg];
                aF[mt][2] = sA[(mr + g)     * GPA + kk + tg + 4];
                aF[mt][3] = sA[(mr + 8 + g) * GPA + kk + tg + 4];
            }
            uint32_t bF[8][2];
            #pragma unroll
            for (int nt = 0; nt < 8; nt++) {
                int n = n0b + nt * 8 + g;
                bF[nt][0] = sB[(kk + tg)     * GPB + n];
                bF[nt][1] = sB[(kk + tg + 4) * GPB + n];
            }
            #pragma unroll
            for (int mt = 0; mt < 2; mt++)
                #pragma unroll
                for (int nt = 0; nt < 8; nt++)
                    mma8(acc[mt][nt], aF[mt][0], aF[mt][1], aF[mt][2], aF[mt][3],
                         bF[nt][0], bF[nt][1]);
        }
    }

    #pragma unroll
    for (int mt = 0; mt < 2; mt++) {
        int r1 = row0 + m0 + mt * 16 + g;
        int r2 = r1 + 8;
        #pragma unroll
        for (int nt = 0; nt < 8; nt++) {
            int c = col0 + n0b + nt * 8 + 2 * tg;
            float2 bv = *(const float2*)(bo + c);
            *(float2*)&out[(size_t)r1 * DIM + c] =
                make_float2(acc[mt][nt][0] + bv.x, acc[mt][nt][1] + bv.y);
            *(float2*)&out[(size_t)r2 * DIM + c] =
                make_float2(acc[mt][nt][2] + bv.x, acc[mt][nt][3] + bv.y);
        }
    }
}

// ---------------- launcher ----------------
extern "C" void kernel_launch(void* const* d_in, const int* in_sizes, int n_in,
                              void* d_out, int out_size) {
    const float* x   = (const float*)d_in[0];
    const float* Wq  = (const float*)d_in[1];
    const float* Wk  = (const float*)d_in[2];
    const float* Wv  = (const float*)d_in[3];
    const float* gq  = (const float*)d_in[4];
    const float* gk  = (const float*)d_in[5];
    const float* Wo  = (const float*)d_in[6];
    const float* bo  = (const float*)d_in[7];
    const float* lnw = (const float*)d_in[8];
    const float* lnb = (const float*)d_in[9];
    float* out = (float*)d_out;

    // attn needs 4 * 64 * 68 * 4 = 69632 B dynamic smem (> 48K default)
    cudaFuncSetAttribute(attn_kernel, cudaFuncAttributeMaxDynamicSharedMemorySize, 4 * 64 * AP * 4);

    ln_kernel<<<MROWS, 256>>>(x, lnw, lnb);
    gemm_qkv<<<dim3(8, 32, 3), 256>>>(x, Wq, Wk, Wv);
    headnorm_kernel<<<(BHN * SEQ) / 8, 256>>>(0, gq);
    headnorm_kernel<<<(BHN * SEQ) / 8, 256>>>(1, gk);
    attn_kernel<<<dim3(SEQ / 64, BHN), 256, 4 * 64 * AP * 4>>>();
    gemm_out<<<dim3(8, 32), 256>>>(Wo, bo, out);
}

// round 8
// speedup vs baseline: 2.4433x; 1.0463x over previous
#include <cuda_runtime.h>
#include <math.h>
#include <stdint.h>

#define DIM   1024
#define BATCH 2
#define SEQ   2048
#define HEADS 16
#define HD    64
#define MROWS (BATCH*SEQ)   /* 4096 */
#define BHN   (BATCH*HEADS) /* 32 */

// ---------------- scratch (device globals: allocation-free) ----------------
__device__ __align__(16) float g_xn[MROWS*DIM];     // layernormed x (tf32 bits)
__device__ __align__(16) float g_xt[MROWS*DIM];     // raw x (tf32 bits)
__device__ __align__(16) float g_Wt[3*DIM*DIM];     // Wq|Wk|Wv (tf32 bits)
__device__ __align__(16) float g_Wot[DIM*DIM];      // Wo (tf32 bits)
__device__ __align__(16) float g_q[BHN*SEQ*HD];     // normalized q (tf32 bits)
__device__ __align__(16) float g_k[BHN*SEQ*HD];     // normalized k (tf32 bits)
__device__ __align__(16) float g_v[BHN*SEQ*HD];     // v * gate_k (tf32 bits)
__device__ __align__(16) float g_gateq[BHN*SEQ];
__device__ __align__(16) float g_coll[MROWS*DIM];   // collapse (tf32 bits)

// ---------------- helpers ----------------
__device__ __forceinline__ uint32_t f2tf(float x) {
    uint32_t u;
    asm("cvt.rna.tf32.f32 %0, %1;" : "=r"(u) : "f"(x));
    return u;
}
__device__ __forceinline__ void mma8(float c[4],
                                     uint32_t a0, uint32_t a1, uint32_t a2, uint32_t a3,
                                     uint32_t b0, uint32_t b1) {
    asm volatile(
        "mma.sync.aligned.m16n8k8.row.col.f32.tf32.tf32.f32 "
        "{%0,%1,%2,%3},{%4,%5,%6,%7},{%8,%9},{%0,%1,%2,%3};"
        : "+f"(c[0]), "+f"(c[1]), "+f"(c[2]), "+f"(c[3])
        : "r"(a0), "r"(a1), "r"(a2), "r"(a3), "r"(b0), "r"(b1));
}
__device__ __forceinline__ void cpa16(uint32_t s, const void* g) {
    asm volatile("cp.async.ca.shared.global [%0], [%1], 16;" :: "r"(s), "l"(g) : "memory");
}
__device__ __forceinline__ void cp_commit() { asm volatile("cp.async.commit_group;" ::: "memory"); }
__device__ __forceinline__ void cp_wait1()  { asm volatile("cp.async.wait_group 1;" ::: "memory"); }
__device__ __forceinline__ void cp_wait0()  { asm volatile("cp.async.wait_group 0;" ::: "memory"); }
__device__ __forceinline__ uint32_t s2u(const void* p) {
    return (uint32_t)__cvta_generic_to_shared(p);
}

// ---------------- weight tf32 pre-convert ----------------
__global__ void __launch_bounds__(256) cvtW_kernel(const float* __restrict__ Wq,
                                                   const float* __restrict__ Wk,
                                                   const float* __restrict__ Wv,
                                                   const float* __restrict__ Wo) {
    int m = blockIdx.y;
    const float* s = (m == 0) ? Wq : (m == 1) ? Wk : (m == 2) ? Wv : Wo;
    float* d = (m == 3) ? g_Wot : (g_Wt + (size_t)m * DIM * DIM);
    int i = (blockIdx.x * 256 + threadIdx.x) * 4;
    float4 v = *(const float4*)(s + i);
    uint4 u = make_uint4(f2tf(v.x), f2tf(v.y), f2tf(v.z), f2tf(v.w));
    *(uint4*)(d + i) = u;
}

// ---------------- LayerNorm (emits tf32 x_norm and tf32 raw x) ----------------
__global__ void __launch_bounds__(256) ln_kernel(const float* __restrict__ x,
                                                 const float* __restrict__ w,
                                                 const float* __restrict__ b) {
    int row = blockIdx.x;
    const float4* xr = (const float4*)(x + (size_t)row * DIM);
    float4 v = xr[threadIdx.x];
    float s  = v.x + v.y + v.z + v.w;
    float ss = v.x*v.x + v.y*v.y + v.z*v.z + v.w*v.w;
    #pragma unroll
    for (int o = 16; o > 0; o >>= 1) {
        s  += __shfl_xor_sync(0xffffffffu, s,  o);
        ss += __shfl_xor_sync(0xffffffffu, ss, o);
    }
    __shared__ float rs[8], rss[8];
    int wid = threadIdx.x >> 5, lane = threadIdx.x & 31;
    if (lane == 0) { rs[wid] = s; rss[wid] = ss; }
    __syncthreads();
    if (wid == 0) {
        float a = (lane < 8) ? rs[lane]  : 0.f;
        float c = (lane < 8) ? rss[lane] : 0.f;
        #pragma unroll
        for (int o = 4; o > 0; o >>= 1) {
            a += __shfl_xor_sync(0xffffffffu, a, o);
            c += __shfl_xor_sync(0xffffffffu, c, o);
        }
        if (lane == 0) { rs[0] = a; rss[0] = c; }
    }
    __syncthreads();
    float mu   = rs[0] * (1.0f / DIM);
    float var  = rss[0] * (1.0f / DIM) - mu * mu;
    float rstd = rsqrtf(var + 1e-5f);
    int c0 = threadIdx.x * 4;
    float4 wv = *(const float4*)(w + c0);
    float4 bv = *(const float4*)(b + c0);
    uint4 yn;
    yn.x = f2tf((v.x - mu) * rstd * wv.x + bv.x);
    yn.y = f2tf((v.y - mu) * rstd * wv.y + bv.y);
    yn.z = f2tf((v.z - mu) * rstd * wv.z + bv.z);
    yn.w = f2tf((v.w - mu) * rstd * wv.w + bv.w);
    *(uint4*)(g_xn + (size_t)row * DIM + c0) = yn;
    uint4 xt = make_uint4(f2tf(v.x), f2tf(v.y), f2tf(v.z), f2tf(v.w));
    *(uint4*)(g_xt + (size_t)row * DIM + c0) = xt;
}

// ---------------- QKV projection GEMM (tf32 mma, 128x128x16, cp.async 2-stage) ----
#define GPA 20    // sA pitch: [m][k] -> frag bank (4g+tg) conflict-free
#define GPB 136   // sB pitch: [k][n] -> frag bank (8tg+g) conflict-free
__global__ void __launch_bounds__(256) gemm_qkv() {
    int mode = blockIdx.z;
    const float* A = (mode == 2) ? g_xt : g_xn;
    const float* W = g_Wt + (size_t)mode * DIM * DIM;
    float* C = (mode == 0) ? g_q : ((mode == 1) ? g_k : g_v);

    __shared__ float sA[2][128 * GPA];
    __shared__ float sB[2][16 * GPB];
    uint32_t sAu = s2u(sA), sBu = s2u(sB);

    int tid = threadIdx.x, lane = tid & 31, wid = tid >> 5;
    int g = lane >> 2, tg = lane & 3;
    int m0  = (wid & 3) * 32;
    int n0b = (wid >> 2) * 64;
    int row0 = blockIdx.y * 128, col0 = blockIdx.x * 128;

    int aRow = tid >> 1, aOff = (tid & 1) * 8;
    int bK = tid >> 4, bN = (tid & 15) * 8;
    const float* gA = A + (size_t)(row0 + aRow) * DIM + aOff;
    const float* gB = W + (size_t)bK * DIM + col0 + bN;

    float acc[2][8][4];
    #pragma unroll
    for (int mt = 0; mt < 2; mt++)
        #pragma unroll
        for (int nt = 0; nt < 8; nt++)
            #pragma unroll
            for (int i = 0; i < 4; i++) acc[mt][nt][i] = 0.f;

    auto issue = [&](int it) {
        int k0 = it * 16, buf = it & 1;
        uint32_t da = sAu + (buf * 128 * GPA + aRow * GPA + aOff) * 4;
        cpa16(da,      gA + k0);
        cpa16(da + 16, gA + k0 + 4);
        uint32_t db = sBu + (buf * 16 * GPB + bK * GPB + bN) * 4;
        const float* gb = gB + (size_t)k0 * DIM;
        cpa16(db,      gb);
        cpa16(db + 16, gb + 4);
    };

    issue(0); cp_commit();
    for (int it = 0; it < 64; it++) {
        if (it < 63) { issue(it + 1); cp_commit(); cp_wait1(); }
        else cp_wait0();
        __syncthreads();
        const float* cA = sA[it & 1];
        const float* cB = sB[it & 1];
        #pragma unroll
        for (int ks = 0; ks < 2; ks++) {
            int kk = ks * 8;
            uint32_t aF[2][4];
            #pragma unroll
            for (int mt = 0; mt < 2; mt++) {
                int mr = m0 + mt * 16;
                aF[mt][0] = ((const uint32_t*)cA)[(mr + g)     * GPA + kk + tg];
                aF[mt][1] = ((const uint32_t*)cA)[(mr + 8 + g) * GPA + kk + tg];
                aF[mt][2] = ((const uint32_t*)cA)[(mr + g)     * GPA + kk + tg + 4];
                aF[mt][3] = ((const uint32_t*)cA)[(mr + 8 + g) * GPA + kk + tg + 4];
            }
            uint32_t bF[8][2];
            #pragma unroll
            for (int nt = 0; nt < 8; nt++) {
                int n = n0b + nt * 8 + g;
                bF[nt][0] = ((const uint32_t*)cB)[(kk + tg)     * GPB + n];
                bF[nt][1] = ((const uint32_t*)cB)[(kk + tg + 4) * GPB + n];
            }
            #pragma unroll
            for (int mt = 0; mt < 2; mt++)
                #pragma unroll
                for (int nt = 0; nt < 8; nt++)
                    mma8(acc[mt][nt], aF[mt][0], aF[mt][1], aF[mt][2], aF[mt][3],
                         bF[nt][0], bF[nt][1]);
        }
        __syncthreads();
    }

    // epilogue: scatter fp32 into head layout [ (b*H+h)*SEQ + t ][ d ]
    #pragma unroll
    for (int mt = 0; mt < 2; mt++) {
        int r1 = row0 + m0 + mt * 16 + g;
        int r2 = r1 + 8;
        int b1 = r1 >> 11, t1 = r1 & 2047;
        int b2 = r2 >> 11, t2 = r2 & 2047;
        #pragma unroll
        for (int nt = 0; nt < 8; nt++) {
            int c = col0 + n0b + nt * 8 + 2 * tg;
            int h = c >> 6, d = c & 63;
            *(float2*)&C[((size_t)(b1 * HEADS + h) * SEQ + t1) * HD + d] =
                make_float2(acc[mt][nt][0], acc[mt][nt][1]);
            *(float2*)&C[((size_t)(b2 * HEADS + h) * SEQ + t2) * HD + d] =
                make_float2(acc[mt][nt][2], acc[mt][nt][3]);
        }
    }
}

// ---------------- per-head l2 normalize + gates (emits tf32 bits) ----------------
__global__ void __launch_bounds__(256) headnorm_kernel(const float* __restrict__ gqv,
                                                       const float* __restrict__ gkv) {
    int isK = blockIdx.y;
    const float* g = isK ? gkv : gqv;
    int row  = (blockIdx.x << 3) + (threadIdx.x >> 5);
    int lane = threadIdx.x & 31;
    float* base = (isK ? g_k : g_q) + (size_t)row * HD;
    float v0 = base[lane], v1 = base[lane + 32];
    float ss = v0 * v0 + v1 * v1;
    #pragma unroll
    for (int o = 16; o > 0; o >>= 1) ss += __shfl_xor_sync(0xffffffffu, ss, o);
    float n = sqrtf(ss);
    float r = 1.0f / fmaxf(n, 1e-12f);
    v0 *= r; v1 *= r;
    base[lane]      = __uint_as_float(f2tf(v0));
    base[lane + 32] = __uint_as_float(f2tf(v1));
    float gt = v0 * g[lane] + v1 * g[lane + 32];
    #pragma unroll
    for (int o = 16; o > 0; o >>= 1) gt += __shfl_xor_sync(0xffffffffu, gt, o);
    if (isK) {
        float* vb = g_v + (size_t)row * HD;
        vb[lane]      = __uint_as_float(f2tf(vb[lane] * gt));
        vb[lane + 32] = __uint_as_float(f2tf(vb[lane + 32] * gt));
    } else if (lane == 0) {
        g_gateq[row] = gt;
    }
}

// ---------------- attention (tf32 mma, cp.async K/V double buffer) ----------------
// 64 q-rows x 64 s-cols per CTA, 8 warps (4x2), warp tile 16x32.
// sQ/sK/sP pitch 68 (frag bank 4g+tg), sV row-major pitch 72 (frag bank 8tg+g).
#define AP 68
#define VP 72
#define SQ_OFF 0
#define SK_OFF (64*AP)                   /* 2 buffers of 64*AP */
#define SV_OFF (SK_OFF + 2*64*AP)        /* 2 buffers of 64*VP */
#define SP_OFF (SV_OFF + 2*64*VP)
#define SM_FLOATS (SP_OFF + 64*AP)       /* 26624 floats = 106496 B */
__global__ void __launch_bounds__(256) attn_kernel() {
    extern __shared__ float sm[];
    float* sQ = sm + SQ_OFF;
    float* sK = sm + SK_OFF;
    float* sV = sm + SV_OFF;
    float* sP = sm + SP_OFF;
    uint32_t sKu = s2u(sK), sVu = s2u(sV);

    int bh = blockIdx.y;
    int t0 = blockIdx.x * 64;
    const float* Q = g_q + ((size_t)bh * SEQ + t0) * HD;
    const float* K = g_k + (size_t)bh * SEQ * HD;
    const float* V = g_v + (size_t)bh * SEQ * HD;

    int tid = threadIdx.x, lane = tid & 31, wid = tid >> 5;
    int g = lane >> 2, tg = lane & 3;
    int m0 = (wid & 3) * 16;
    int n0 = (wid >> 2) * 32;

    // preload Q tile (already tf32 bits)
    #pragma unroll
    for (int f = 0; f < 4; f++) {
        int e = tid + f * 256;
        int r = e >> 4, o = (e & 15) * 4;
        *(float4*)&sQ[r * AP + o] = *(const float4*)(Q + r * HD + o);
    }

    auto issueKV = [&](int it) {
        int s0 = it * 64, buf = it & 1;
        #pragma unroll
        for (int f = 0; f < 4; f++) {
            int e = tid + f * 256;
            int r = e >> 4, o = (e & 15) * 4;
            cpa16(sKu + (buf * 64 * AP + r * AP + o) * 4, K + (size_t)(s0 + r) * HD + o);
            cpa16(sVu + (buf * 64 * VP + r * VP + o) * 4, V + (size_t)(s0 + r) * HD + o);
        }
    };

    float O[4][4];
    #pragma unroll
    for (int nt = 0; nt < 4; nt++)
        #pragma unroll
        for (int i = 0; i < 4; i++) O[nt][i] = 0.f;

    issueKV(0); cp_commit();
    for (int it = 0; it < SEQ / 64; it++) {
        if (it < SEQ / 64 - 1) { issueKV(it + 1); cp_commit(); cp_wait1(); }
        else cp_wait0();
        __syncthreads();
        const uint32_t* cK = (const uint32_t*)(sK + (it & 1) * 64 * AP);
        const uint32_t* cV = (const uint32_t*)(sV + (it & 1) * 64 * VP);
        const uint32_t* cQ = (const uint32_t*)sQ;
        uint32_t* cP = (uint32_t*)sP;

        // S = Q @ K^T
        float S[4][4];
        #pragma unroll
        for (int nt = 0; nt < 4; nt++)
            #pragma unroll
            for (int i = 0; i < 4; i++) S[nt][i] = 0.f;
        #pragma unroll
        for (int ks = 0; ks < 8; ks++) {
            int kk = ks * 8;
            uint32_t a0 = cQ[(m0 + g)     * AP + kk + tg];
            uint32_t a1 = cQ[(m0 + 8 + g) * AP + kk + tg];
            uint32_t a2 = cQ[(m0 + g)     * AP + kk + tg + 4];
            uint32_t a3 = cQ[(m0 + 8 + g) * AP + kk + tg + 4];
            #pragma unroll
            for (int nt = 0; nt < 4; nt++) {
                int n = n0 + nt * 8 + g;
                mma8(S[nt], a0, a1, a2, a3,
                     cK[n * AP + kk + tg], cK[n * AP + kk + tg + 4]);
            }
        }

        // sigmoid -> sP (tf32, A-operand layout [t][s])
        #pragma unroll
        for (int nt = 0; nt < 4; nt++) {
            int c = n0 + nt * 8 + 2 * tg;
            float p0 = 1.0f / (1.0f + __expf(-(S[nt][0] - 0.29514f) * 15.0f));
            float p1 = 1.0f / (1.0f + __expf(-(S[nt][1] - 0.29514f) * 15.0f));
            float p2 = 1.0f / (1.0f + __expf(-(S[nt][2] - 0.29514f) * 15.0f));
            float p3 = 1.0f / (1.0f + __expf(-(S[nt][3] - 0.29514f) * 15.0f));
            cP[(m0 + g)     * AP + c]     = f2tf(p0);
            cP[(m0 + g)     * AP + c + 1] = f2tf(p1);
            cP[(m0 + 8 + g) * AP + c]     = f2tf(p2);
            cP[(m0 + 8 + g) * AP + c + 1] = f2tf(p3);
        }
        __syncthreads();

        // O += P @ V  (B frags read straight from row-major V: B[k][n] = sV[k*VP + n])
        #pragma unroll
        for (int ks = 0; ks < 8; ks++) {
            int kk = ks * 8;
            uint32_t a0 = cP[(m0 + g)     * AP + kk + tg];
            uint32_t a1 = cP[(m0 + 8 + g) * AP + kk + tg];
            uint32_t a2 = cP[(m0 + g)     * AP + kk + tg + 4];
            uint32_t a3 = cP[(m0 + 8 + g) * AP + kk + tg + 4];
            #pragma unroll
            for (int nt = 0; nt < 4; nt++) {
                int n = n0 + nt * 8 + g;
                mma8(O[nt], a0, a1, a2, a3,
                     cV[(kk + tg) * VP + n], cV[(kk + tg + 4) * VP + n]);
            }
        }
        __syncthreads();
    }

    // epilogue: * gate_q, emit tf32 bits into row-major collapse layout
    int b = bh >> 4, h = bh & 15;
    int t1 = t0 + m0 + g, t2 = t1 + 8;
    float gq1 = g_gateq[(size_t)bh * SEQ + t1];
    float gq2 = g_gateq[(size_t)bh * SEQ + t2];
    #pragma unroll
    for (int nt = 0; nt < 4; nt++) {
        int d = n0 + nt * 8 + 2 * tg;
        float* p1 = &g_coll[((size_t)(b * SEQ + t1) * HEADS + h) * HD + d];
        float* p2 = &g_coll[((size_t)(b * SEQ + t2) * HEADS + h) * HD + d];
        *(float2*)p1 = make_float2(__uint_as_float(f2tf(O[nt][0] * gq1)),
                                   __uint_as_float(f2tf(O[nt][1] * gq1)));
        *(float2*)p2 = make_float2(__uint_as_float(f2tf(O[nt][2] * gq2)),
                                   __uint_as_float(f2tf(O[nt][3] * gq2)));
    }
}

// ---------------- output GEMM + bias (tf32 mma, cp.async 2-stage) ----------------
__global__ void __launch_bounds__(256) gemm_out(const float* __restrict__ bo,
                                                float* __restrict__ out) {
    __shared__ float sA[2][128 * GPA];
    __shared__ float sB[2][16 * GPB];
    uint32_t sAu = s2u(sA), sBu = s2u(sB);

    int tid = threadIdx.x, lane = tid & 31, wid = tid >> 5;
    int g = lane >> 2, tg = lane & 3;
    int m0  = (wid & 3) * 32;
    int n0b = (wid >> 2) * 64;
    int row0 = blockIdx.y * 128, col0 = blockIdx.x * 128;

    int aRow = tid >> 1, aOff = (tid & 1) * 8;
    int bK = tid >> 4, bN = (tid & 15) * 8;
    const float* gA = g_coll + (size_t)(row0 + aRow) * DIM + aOff;
    const float* gB = g_Wot + (size_t)bK * DIM + col0 + bN;

    float acc[2][8][4];
    #pragma unroll
    for (int mt = 0; mt < 2; mt++)
        #pragma unroll
        for (int nt = 0; nt < 8; nt++)
            #pragma unroll
            for (int i = 0; i < 4; i++) acc[mt][nt][i] = 0.f;

    auto issue = [&](int it) {
        int k0 = it * 16, buf = it & 1;
        uint32_t da = sAu + (buf * 128 * GPA + aRow * GPA + aOff) * 4;
        cpa16(da,      gA + k0);
        cpa16(da + 16, gA + k0 + 4);
        uint32_t db = sBu + (buf * 16 * GPB + bK * GPB + bN) * 4;
        const float* gb = gB + (size_t)k0 * DIM;
        cpa16(db,      gb);
        cpa16(db + 16, gb + 4);
    };

    issue(0); cp_commit();
    for (int it = 0; it < 64; it++) {
        if (it < 63) { issue(it + 1); cp_commit(); cp_wait1(); }
        else cp_wait0();
        __syncthreads();
        const uint32_t* cA = (const uint32_t*)sA[it & 1];
        const uint32_t* cB = (const uint32_t*)sB[it & 1];
        #pragma unroll
        for (int ks = 0; ks < 2; ks++) {
            int kk = ks * 8;
            uint32_t aF[2][4];
            #pragma unroll
            for (int mt = 0; mt < 2; mt++) {
                int mr = m0 + mt * 16;
                aF[mt][0] = cA[(mr + g)     * GPA + kk + tg];
                aF[mt][1] = cA[(mr + 8 + g) * GPA + kk + tg];
                aF[mt][2] = cA[(mr + g)     * GPA + kk + tg + 4];
                aF[mt][3] = cA[(mr + 8 + g) * GPA + kk + tg + 4];
            }
            uint32_t bF[8][2];
            #pragma unroll
            for (int nt = 0; nt < 8; nt++) {
                int n = n0b + nt * 8 + g;
                bF[nt][0] = cB[(kk + tg)     * GPB + n];
                bF[nt][1] = cB[(kk + tg + 4) * GPB + n];
            }
            #pragma unroll
            for (int mt = 0; mt < 2; mt++)
                #pragma unroll
                for (int nt = 0; nt < 8; nt++)
                    mma8(acc[mt][nt], aF[mt][0], aF[mt][1], aF[mt][2], aF[mt][3],
                         bF[nt][0], bF[nt][1]);
        }
        __syncthreads();
    }

    #pragma unroll
    for (int mt = 0; mt < 2; mt++) {
        int r1 = row0 + m0 + mt * 16 + g;
        int r2 = r1 + 8;
        #pragma unroll
        for (int nt = 0; nt < 8; nt++) {
            int c = col0 + n0b + nt * 8 + 2 * tg;
            float2 bv = *(const float2*)(bo + c);
            *(float2*)&out[(size_t)r1 * DIM + c] =
                make_float2(acc[mt][nt][0] + bv.x, acc[mt][nt][1] + bv.y);
            *(float2*)&out[(size_t)r2 * DIM + c] =
                make_float2(acc[mt][nt][2] + bv.x, acc[mt][nt][3] + bv.y);
        }
    }
}

// ---------------- launcher ----------------
extern "C" void kernel_launch(void* const* d_in, const int* in_sizes, int n_in,
                              void* d_out, int out_size) {
    const float* x   = (const float*)d_in[0];
    const float* Wq  = (const float*)d_in[1];
    const float* Wk  = (const float*)d_in[2];
    const float* Wv  = (const float*)d_in[3];
    const float* gq  = (const float*)d_in[4];
    const float* gk  = (const float*)d_in[5];
    const float* Wo  = (const float*)d_in[6];
    const float* bo  = (const float*)d_in[7];
    const float* lnw = (const float*)d_in[8];
    const float* lnb = (const float*)d_in[9];
    float* out = (float*)d_out;

    cudaFuncSetAttribute(attn_kernel, cudaFuncAttributeMaxDynamicSharedMemorySize,
                         SM_FLOATS * 4);

    cvtW_kernel<<<dim3(DIM * DIM / 1024, 4), 256>>>(Wq, Wk, Wv, Wo);
    ln_kernel<<<MROWS, 256>>>(x, lnw, lnb);
    gemm_qkv<<<dim3(8, 32, 3), 256>>>();
    headnorm_kernel<<<dim3((BHN * SEQ) / 8, 2), 256>>>(gq, gk);
    attn_kernel<<<dim3(SEQ / 64, BHN), 256, SM_FLOATS * 4>>>();
    gemm_out<<<dim3(8, 32), 256>>>(bo, out);
}

// round 9
// speedup vs baseline: 3.6266x; 1.4843x over previous
#include <cuda_runtime.h>
#include <cuda_fp16.h>
#include <math.h>
#include <stdint.h>

#define DIM   1024
#define BATCH 2
#define SEQ   2048
#define HEADS 16
#define HD    64
#define MROWS (BATCH*SEQ)   /* 4096 */
#define BHN   (BATCH*HEADS) /* 32 */

// ---------------- scratch (device globals: allocation-free) ----------------
__device__ __align__(16) __half g_xn[MROWS*DIM];    // layernormed x (fp16)
__device__ __align__(16) __half g_xt[MROWS*DIM];    // raw x (fp16)
__device__ __align__(16) __half g_Wt[3*DIM*DIM];    // Wq|Wk|Wv (fp16)
__device__ __align__(16) __half g_Wot[DIM*DIM];     // Wo (fp16)
__device__ __align__(16) __half g_q[BHN*SEQ*HD];    // normalized q (fp16)
__device__ __align__(16) __half g_k[BHN*SEQ*HD];    // normalized k (fp16)
__device__ __align__(16) __half g_v[BHN*SEQ*HD];    // v * gate_k (fp16)
__device__ float g_gateq[BHN*SEQ];
__device__ __align__(16) __half g_coll[MROWS*DIM];  // collapse (fp16)

// ---------------- helpers ----------------
__device__ __forceinline__ void mma16(float c[4],
                                      uint32_t a0, uint32_t a1, uint32_t a2, uint32_t a3,
                                      uint32_t b0, uint32_t b1) {
    asm volatile(
        "mma.sync.aligned.m16n8k16.row.col.f32.f16.f16.f32 "
        "{%0,%1,%2,%3},{%4,%5,%6,%7},{%8,%9},{%0,%1,%2,%3};"
        : "+f"(c[0]), "+f"(c[1]), "+f"(c[2]), "+f"(c[3])
        : "r"(a0), "r"(a1), "r"(a2), "r"(a3), "r"(b0), "r"(b1));
}
__device__ __forceinline__ void ldsm4(uint32_t r[4], uint32_t addr) {
    asm volatile("ldmatrix.sync.aligned.m8n8.x4.shared.b16 {%0,%1,%2,%3}, [%4];"
                 : "=r"(r[0]), "=r"(r[1]), "=r"(r[2]), "=r"(r[3]) : "r"(addr));
}
__device__ __forceinline__ void ldsm4t(uint32_t r[4], uint32_t addr) {
    asm volatile("ldmatrix.sync.aligned.m8n8.x4.trans.shared.b16 {%0,%1,%2,%3}, [%4];"
                 : "=r"(r[0]), "=r"(r[1]), "=r"(r[2]), "=r"(r[3]) : "r"(addr));
}
__device__ __forceinline__ void cpa16(uint32_t s, const void* g) {
    asm volatile("cp.async.ca.shared.global [%0], [%1], 16;" :: "r"(s), "l"(g) : "memory");
}
__device__ __forceinline__ void cp_commit() { asm volatile("cp.async.commit_group;" ::: "memory"); }
__device__ __forceinline__ void cp_wait1()  { asm volatile("cp.async.wait_group 1;" ::: "memory"); }
__device__ __forceinline__ void cp_wait0()  { asm volatile("cp.async.wait_group 0;" ::: "memory"); }
__device__ __forceinline__ uint32_t s2u(const void* p) {
    return (uint32_t)__cvta_generic_to_shared(p);
}

// ---------------- weight fp16 pre-convert ----------------
__global__ void __launch_bounds__(256) cvtW_kernel(const float* __restrict__ Wq,
                                                   const float* __restrict__ Wk,
                                                   const float* __restrict__ Wv,
                                                   const float* __restrict__ Wo) {
    int m = blockIdx.y;
    const float* s = (m == 0) ? Wq : (m == 1) ? Wk : (m == 2) ? Wv : Wo;
    __half* d = (m == 3) ? g_Wot : (g_Wt + (size_t)m * DIM * DIM);
    int i = (blockIdx.x * 256 + threadIdx.x) * 4;
    float4 v = *(const float4*)(s + i);
    ((__half2*)(d + i))[0] = __floats2half2_rn(v.x, v.y);
    ((__half2*)(d + i))[1] = __floats2half2_rn(v.z, v.w);
}

// ---------------- LayerNorm (emits fp16 x_norm and fp16 raw x) ----------------
__global__ void __launch_bounds__(256) ln_kernel(const float* __restrict__ x,
                                                 const float* __restrict__ w,
                                                 const float* __restrict__ b) {
    int row = blockIdx.x;
    const float4* xr = (const float4*)(x + (size_t)row * DIM);
    float4 v = xr[threadIdx.x];
    float s  = v.x + v.y + v.z + v.w;
    float ss = v.x*v.x + v.y*v.y + v.z*v.z + v.w*v.w;
    #pragma unroll
    for (int o = 16; o > 0; o >>= 1) {
        s  += __shfl_xor_sync(0xffffffffu, s,  o);
        ss += __shfl_xor_sync(0xffffffffu, ss, o);
    }
    __shared__ float rs[8], rss[8];
    int wid = threadIdx.x >> 5, lane = threadIdx.x & 31;
    if (lane == 0) { rs[wid] = s; rss[wid] = ss; }
    __syncthreads();
    if (wid == 0) {
        float a = (lane < 8) ? rs[lane]  : 0.f;
        float c = (lane < 8) ? rss[lane] : 0.f;
        #pragma unroll
        for (int o = 4; o > 0; o >>= 1) {
            a += __shfl_xor_sync(0xffffffffu, a, o);
            c += __shfl_xor_sync(0xffffffffu, c, o);
        }
        if (lane == 0) { rs[0] = a; rss[0] = c; }
    }
    __syncthreads();
    float mu   = rs[0] * (1.0f / DIM);
    float var  = rss[0] * (1.0f / DIM) - mu * mu;
    float rstd = rsqrtf(var + 1e-5f);
    int c0 = threadIdx.x * 4;
    float4 wv = *(const float4*)(w + c0);
    float4 bv = *(const float4*)(b + c0);
    float y0 = (v.x - mu) * rstd * wv.x + bv.x;
    float y1 = (v.y - mu) * rstd * wv.y + bv.y;
    float y2 = (v.z - mu) * rstd * wv.z + bv.z;
    float y3 = (v.w - mu) * rstd * wv.w + bv.w;
    __half* dn = g_xn + (size_t)row * DIM + c0;
    ((__half2*)dn)[0] = __floats2half2_rn(y0, y1);
    ((__half2*)dn)[1] = __floats2half2_rn(y2, y3);
    __half* dt = g_xt + (size_t)row * DIM + c0;
    ((__half2*)dt)[0] = __floats2half2_rn(v.x, v.y);
    ((__half2*)dt)[1] = __floats2half2_rn(v.z, v.w);
}

// ---------------- QKV projection GEMM (fp16 mma, 128x128x32, cp.async 2-stage) ----
#define PA 40     // sA pitch (halves): 20-word rows -> ldsm 8-row perm conflict-free
#define PB 136    // sB pitch (halves): 68-word rows -> 4r perm conflict-free
__global__ void __launch_bounds__(256) gemm_qkv() {
    int mode = blockIdx.z;
    const __half* A = (mode == 2) ? g_xt : g_xn;
    const __half* W = g_Wt + (size_t)mode * DIM * DIM;
    __half* C = (mode == 0) ? g_q : ((mode == 1) ? g_k : g_v);

    __shared__ __half sA[2][128 * PA];
    __shared__ __half sB[2][32 * PB];
    uint32_t sAu = s2u(sA), sBu = s2u(sB);

    int tid = threadIdx.x, lane = tid & 31, wid = tid >> 5;
    int g = lane >> 2, tg = lane & 3;
    int m0  = (wid & 3) * 32;
    int n0b = (wid >> 2) * 64;
    int row0 = blockIdx.y * 128, col0 = blockIdx.x * 128;

    int aRow = tid >> 1, aOff = (tid & 1) * 16;           // halves
    int bK = tid >> 3, bN = (tid & 7) * 16;               // halves
    const __half* gA = A + (size_t)(row0 + aRow) * DIM + aOff;
    const __half* gB = W + (size_t)bK * DIM + col0 + bN;

    float acc[2][8][4];
    #pragma unroll
    for (int mt = 0; mt < 2; mt++)
        #pragma unroll
        for (int nt = 0; nt < 8; nt++)
            #pragma unroll
            for (int i = 0; i < 4; i++) acc[mt][nt][i] = 0.f;

    auto issue = [&](int it) {
        int k0 = it * 32, buf = it & 1;
        uint32_t da = sAu + (buf * 128 * PA + aRow * PA + aOff) * 2;
        cpa16(da,      gA + k0);
        cpa16(da + 16, gA + k0 + 8);
        uint32_t db = sBu + (buf * 32 * PB + bK * PB + bN) * 2;
        const __half* gb = gB + (size_t)k0 * DIM;
        cpa16(db,      gb);
        cpa16(db + 16, gb + 8);
    };

    int lr = lane & 15, lh = (lane >> 4) * 8;
    issue(0); cp_commit();
    for (int it = 0; it < 32; it++) {
        if (it < 31) { issue(it + 1); cp_commit(); cp_wait1(); }
        else cp_wait0();
        __syncthreads();
        int buf = it & 1;
        uint32_t aB = sAu + buf * (128 * PA * 2);
        uint32_t bB = sBu + buf * (32 * PB * 2);
        #pragma unroll
        for (int ks = 0; ks < 2; ks++) {
            int kk = ks * 16;
            uint32_t aF[2][4];
            #pragma unroll
            for (int mt = 0; mt < 2; mt++)
                ldsm4(aF[mt], aB + ((m0 + mt * 16 + lr) * PA + kk + lh) * 2);
            uint32_t bF[4][4];
            #pragma unroll
            for (int ntp = 0; ntp < 4; ntp++)
                ldsm4t(bF[ntp], bB + ((kk + lr) * PB + n0b + ntp * 16 + lh) * 2);
            #pragma unroll
            for (int mt = 0; mt < 2; mt++)
                #pragma unroll
                for (int ntp = 0; ntp < 4; ntp++) {
                    mma16(acc[mt][ntp*2],   aF[mt][0], aF[mt][1], aF[mt][2], aF[mt][3],
                          bF[ntp][0], bF[ntp][1]);
                    mma16(acc[mt][ntp*2+1], aF[mt][0], aF[mt][1], aF[mt][2], aF[mt][3],
                          bF[ntp][2], bF[ntp][3]);
                }
        }
        __syncthreads();
    }

    // epilogue: fp16 scatter into head layout [ (b*H+h)*SEQ + t ][ d ]
    #pragma unroll
    for (int mt = 0; mt < 2; mt++) {
        int r1 = row0 + m0 + mt * 16 + g;
        int r2 = r1 + 8;
        int b1 = r1 >> 11, t1 = r1 & 2047;
        int b2 = r2 >> 11, t2 = r2 & 2047;
        #pragma unroll
        for (int nt = 0; nt < 8; nt++) {
            int c = col0 + n0b + nt * 8 + 2 * tg;
            int hh = c >> 6, d = c & 63;
            *(__half2*)&C[((size_t)(b1 * HEADS + hh) * SEQ + t1) * HD + d] =
                __floats2half2_rn(acc[mt][nt][0], acc[mt][nt][1]);
            *(__half2*)&C[((size_t)(b2 * HEADS + hh) * SEQ + t2) * HD + d] =
                __floats2half2_rn(acc[mt][nt][2], acc[mt][nt][3]);
        }
    }
}

// ---------------- per-head l2 normalize + gates (fp16 storage) ----------------
__global__ void __launch_bounds__(256) headnorm_kernel(const float* __restrict__ gqv,
                                                       const float* __restrict__ gkv) {
    int isK = blockIdx.y;
    const float* g = isK ? gqv + 0 : gqv;   // placeholder, fixed below
    g = isK ? gkv : gqv;
    int row  = (blockIdx.x << 3) + (threadIdx.x >> 5);
    int lane = threadIdx.x & 31;
    __half* base = (isK ? g_k : g_q) + (size_t)row * HD;
    __half2 h = ((__half2*)base)[lane];
    float v0 = __low2float(h), v1 = __high2float(h);
    float ss = v0 * v0 + v1 * v1;
    #pragma unroll
    for (int o = 16; o > 0; o >>= 1) ss += __shfl_xor_sync(0xffffffffu, ss, o);
    float n = sqrtf(ss);
    float r = 1.0f / fmaxf(n, 1e-12f);
    v0 *= r; v1 *= r;
    ((__half2*)base)[lane] = __floats2half2_rn(v0, v1);
    float2 gv = ((const float2*)g)[lane];
    float gt = v0 * gv.x + v1 * gv.y;
    #pragma unroll
    for (int o = 16; o > 0; o >>= 1) gt += __shfl_xor_sync(0xffffffffu, gt, o);
    if (isK) {
        __half* vb = g_v + (size_t)row * HD;
        __half2 hv = ((__half2*)vb)[lane];
        ((__half2*)vb)[lane] = __floats2half2_rn(__low2float(hv) * gt, __high2float(hv) * gt);
    } else if (lane == 0) {
        g_gateq[row] = gt;
    }
}

// ---------------- attention (fp16 mma + ldmatrix, cp.async K/V double buffer) ----
// 64 q x 64 s per CTA, 8 warps (4x2), warp tile 16x32. All pitches 72 halves.
#define ATP 72
#define TILE_H (64*ATP)  /* halves per 64-row tile */
#define SQO 0
#define SKO TILE_H
#define SVO (TILE_H*3)
#define SPO (TILE_H*5)
#define SMH (TILE_H*6)   /* 27648 halves = 55296 B */
__global__ void __launch_bounds__(256) attn_kernel() {
    extern __shared__ __half smh[];
    __half* sQ = smh + SQO;
    __half* sK = smh + SKO;
    __half* sV = smh + SVO;
    __half* sP = smh + SPO;
    uint32_t qB = s2u(sQ), kB0 = s2u(sK), vB0 = s2u(sV), pB = s2u(sP);

    int bh = blockIdx.y;
    int t0 = blockIdx.x * 64;
    const __half* Q = g_q + ((size_t)bh * SEQ + t0) * HD;
    const __half* K = g_k + (size_t)bh * SEQ * HD;
    const __half* V = g_v + (size_t)bh * SEQ * HD;

    int tid = threadIdx.x, lane = tid & 31, wid = tid >> 5;
    int g = lane >> 2, tg = lane & 3;
    int m0 = (wid & 3) * 16;
    int n0 = (wid >> 2) * 32;
    int lr = lane & 15, lh = (lane >> 4) * 8;
    int lr8 = ((lane >> 4) << 3) + (lane & 7), lk8 = ((lane >> 3) & 1) * 8;

    // preload Q tile (fp16)
    #pragma unroll
    for (int f = 0; f < 2; f++) {
        int e = tid + f * 256;
        int r = e >> 3, o = (e & 7) * 8;
        *(uint4*)&sQ[r * ATP + o] = *(const uint4*)(Q + r * HD + o);
    }

    auto issueKV = [&](int it) {
        int s0 = it * 64, buf = it & 1;
        #pragma unroll
        for (int f = 0; f < 2; f++) {
            int e = tid + f * 256;
            int r = e >> 3, o = (e & 7) * 8;
            cpa16(kB0 + (buf * TILE_H + r * ATP + o) * 2, K + (size_t)(s0 + r) * HD + o);
            cpa16(vB0 + (buf * TILE_H + r * ATP + o) * 2, V + (size_t)(s0 + r) * HD + o);
        }
    };

    float O[4][4];
    #pragma unroll
    for (int nt = 0; nt < 4; nt++)
        #pragma unroll
        for (int i = 0; i < 4; i++) O[nt][i] = 0.f;

    issueKV(0); cp_commit();
    for (int it = 0; it < SEQ / 64; it++) {
        if (it < SEQ / 64 - 1) { issueKV(it + 1); cp_commit(); cp_wait1(); }
        else cp_wait0();
        __syncthreads();
        int buf = it & 1;
        uint32_t kBa = kB0 + buf * TILE_H * 2;
        uint32_t vBa = vB0 + buf * TILE_H * 2;

        // S = Q @ K^T   (A frag from sQ, B frag from sK rows: pairs contiguous in d)
        float S[4][4];
        #pragma unroll
        for (int nt = 0; nt < 4; nt++)
            #pragma unroll
            for (int i = 0; i < 4; i++) S[nt][i] = 0.f;
        #pragma unroll
        for (int ks = 0; ks < 4; ks++) {
            int kk = ks * 16;
            uint32_t aF[4];
            ldsm4(aF, qB + ((m0 + lr) * ATP + kk + lh) * 2);
            #pragma unroll
            for (int ntp = 0; ntp < 2; ntp++) {
                uint32_t bF[4];
                ldsm4(bF, kBa + ((n0 + ntp * 16 + lr8) * ATP + kk + lk8) * 2);
                mma16(S[ntp*2],   aF[0], aF[1], aF[2], aF[3], bF[0], bF[1]);
                mma16(S[ntp*2+1], aF[0], aF[1], aF[2], aF[3], bF[2], bF[3]);
            }
        }

        // sigmoid -> sP (fp16, [t][s] layout)
        uint32_t* cP = (uint32_t*)sP;
        #pragma unroll
        for (int nt = 0; nt < 4; nt++) {
            int ci = (n0 + nt * 8) / 2 + tg;
            float p0 = 1.0f / (1.0f + __expf(-(S[nt][0] - 0.29514f) * 15.0f));
            float p1 = 1.0f / (1.0f + __expf(-(S[nt][1] - 0.29514f) * 15.0f));
            float p2 = 1.0f / (1.0f + __expf(-(S[nt][2] - 0.29514f) * 15.0f));
            float p3 = 1.0f / (1.0f + __expf(-(S[nt][3] - 0.29514f) * 15.0f));
            __half2 hA = __floats2half2_rn(p0, p1);
            __half2 hB = __floats2half2_rn(p2, p3);
            cP[(m0 + g) * (ATP/2) + ci]     = *(uint32_t*)&hA;
            cP[(m0 + 8 + g) * (ATP/2) + ci] = *(uint32_t*)&hB;
        }
        __syncthreads();

        // O += P @ V   (A from sP, B from sV via ldsm trans: k=s, n=d)
        #pragma unroll
        for (int ks = 0; ks < 4; ks++) {
            int kk = ks * 16;
            uint32_t aF[4];
            ldsm4(aF, pB + ((m0 + lr) * ATP + kk + lh) * 2);
            #pragma unroll
            for (int ntp = 0; ntp < 2; ntp++) {
                uint32_t bF[4];
                ldsm4t(bF, vBa + ((kk + lr) * ATP + n0 + ntp * 16 + lh) * 2);
                mma16(O[ntp*2],   aF[0], aF[1], aF[2], aF[3], bF[0], bF[1]);
                mma16(O[ntp*2+1], aF[0], aF[1], aF[2], aF[3], bF[2], bF[3]);
            }
        }
        __syncthreads();
    }

    // epilogue: * gate_q, emit fp16 into row-major collapse layout
    int b = bh >> 4, hh = bh & 15;
    int t1 = t0 + m0 + g, t2 = t1 + 8;
    float gq1 = g_gateq[(size_t)bh * SEQ + t1];
    float gq2 = g_gateq[(size_t)bh * SEQ + t2];
    #pragma unroll
    for (int nt = 0; nt < 4; nt++) {
        int d = n0 + nt * 8 + 2 * tg;
        *(__half2*)&g_coll[((size_t)(b * SEQ + t1) * HEADS + hh) * HD + d] =
            __floats2half2_rn(O[nt][0] * gq1, O[nt][1] * gq1);
        *(__half2*)&g_coll[((size_t)(b * SEQ + t2) * HEADS + hh) * HD + d] =
            __floats2half2_rn(O[nt][2] * gq2, O[nt][3] * gq2);
    }
}

// ---------------- output GEMM + bias (fp16 mma, cp.async 2-stage) ----------------
__global__ void __launch_bounds__(256) gemm_out(const float* __restrict__ bo,
                                                float* __restrict__ out) {
    __shared__ __half sA[2][128 * PA];
    __shared__ __half sB[2][32 * PB];
    uint32_t sAu = s2u(sA), sBu = s2u(sB);

    int tid = threadIdx.x, lane = tid & 31, wid = tid >> 5;
    int g = lane >> 2, tg = lane & 3;
    int m0  = (wid & 3) * 32;
    int n0b = (wid >> 2) * 64;
    int row0 = blockIdx.y * 128, col0 = blockIdx.x * 128;

    int aRow = tid >> 1, aOff = (tid & 1) * 16;
    int bK = tid >> 3, bN = (tid & 7) * 16;
    const __half* gA = g_coll + (size_t)(row0 + aRow) * DIM + aOff;
    const __half* gB = g_Wot + (size_t)bK * DIM + col0 + bN;

    float acc[2][8][4];
    #pragma unroll
    for (int mt = 0; mt < 2; mt++)
        #pragma unroll
        for (int nt = 0; nt < 8; nt++)
            #pragma unroll
            for (int i = 0; i < 4; i++) acc[mt][nt][i] = 0.f;

    auto issue = [&](int it) {
        int k0 = it * 32, buf = it & 1;
        uint32_t da = sAu + (buf * 128 * PA + aRow * PA + aOff) * 2;
        cpa16(da,      gA + k0);
        cpa16(da + 16, gA + k0 + 8);
        uint32_t db = sBu + (buf * 32 * PB + bK * PB + bN) * 2;
        const __half* gb = gB + (size_t)k0 * DIM;
        cpa16(db,      gb);
        cpa16(db + 16, gb + 8);
    };

    int lr = lane & 15, lh = (lane >> 4) * 8;
    issue(0); cp_commit();
    for (int it = 0; it < 32; it++) {
        if (it < 31) { issue(it + 1); cp_commit(); cp_wait1(); }
        else cp_wait0();
        __syncthreads();
        int buf = it & 1;
        uint32_t aB = sAu + buf * (128 * PA * 2);
        uint32_t bB = sBu + buf * (32 * PB * 2);
        #pragma unroll
        for (int ks = 0; ks < 2; ks++) {
            int kk = ks * 16;
            uint32_t aF[2][4];
            #pragma unroll
            for (int mt = 0; mt < 2; mt++)
                ldsm4(aF[mt], aB + ((m0 + mt * 16 + lr) * PA + kk + lh) * 2);
            uint32_t bF[4][4];
            #pragma unroll
            for (int ntp = 0; ntp < 4; ntp++)
                ldsm4t(bF[ntp], bB + ((kk + lr) * PB + n0b + ntp * 16 + lh) * 2);
            #pragma unroll
            for (int mt = 0; mt < 2; mt++)
                #pragma unroll
                for (int ntp = 0; ntp < 4; ntp++) {
                    mma16(acc[mt][ntp*2],   aF[mt][0], aF[mt][1], aF[mt][2], aF[mt][3],
                          bF[ntp][0], bF[ntp][1]);
                    mma16(acc[mt][ntp*2+1], aF[mt][0], aF[mt][1], aF[mt][2], aF[mt][3],
                          bF[ntp][2], bF[ntp][3]);
                }
        }
        __syncthreads();
    }

    #pragma unroll
    for (int mt = 0; mt < 2; mt++) {
        int r1 = row0 + m0 + mt * 16 + g;
        int r2 = r1 + 8;
        #pragma unroll
        for (int nt = 0; nt < 8; nt++) {
            int c = col0 + n0b + nt * 8 + 2 * tg;
            float2 bv = *(const float2*)(bo + c);
            *(float2*)&out[(size_t)r1 * DIM + c] =
                make_float2(acc[mt][nt][0] + bv.x, acc[mt][nt][1] + bv.y);
            *(float2*)&out[(size_t)r2 * DIM + c] =
                make_float2(acc[mt][nt][2] + bv.x, acc[mt][nt][3] + bv.y);
        }
    }
}

// ---------------- launcher ----------------
extern "C" void kernel_launch(void* const* d_in, const int* in_sizes, int n_in,
                              void* d_out, int out_size) {
    const float* x   = (const float*)d_in[0];
    const float* Wq  = (const float*)d_in[1];
    const float* Wk  = (const float*)d_in[2];
    const float* Wv  = (const float*)d_in[3];
    const float* gq  = (const float*)d_in[4];
    const float* gk  = (const float*)d_in[5];
    const float* Wo  = (const float*)d_in[6];
    const float* bo  = (const float*)d_in[7];
    const float* lnw = (const float*)d_in[8];
    const float* lnb = (const float*)d_in[9];
    float* out = (float*)d_out;

    cudaFuncSetAttribute(attn_kernel, cudaFuncAttributeMaxDynamicSharedMemorySize,
                         SMH * 2);

    cvtW_kernel<<<dim3(DIM * DIM / 1024, 4), 256>>>(Wq, Wk, Wv, Wo);
    ln_kernel<<<MROWS, 256>>>(x, lnw, lnb);
    gemm_qkv<<<dim3(8, 32, 3), 256>>>();
    headnorm_kernel<<<dim3((BHN * SEQ) / 8, 2), 256>>>(gq, gk);
    attn_kernel<<<dim3(SEQ / 64, BHN), 256, SMH * 2>>>();
    gemm_out<<<dim3(8, 32), 256>>>(bo, out);
}

// round 11
// speedup vs baseline: 6.5056x; 1.7939x over previous
#include <cuda_runtime.h>
#include <cuda_fp16.h>
#include <math.h>
#include <stdint.h>

#define DIM   1024
#define BATCH 2
#define SEQ   2048
#define HEADS 16
#define HD    64
#define MROWS (BATCH*SEQ)   /* 4096 */
#define BHN   (BATCH*HEADS) /* 32 */
#define TH    0.29514f
#define SHARP 15.0f

// ---------------- scratch (device globals: allocation-free) ----------------
__device__ __align__(16) __half g_xn[MROWS*DIM];    // layernormed x (fp16)
__device__ __align__(16) __half g_xt[MROWS*DIM];    // raw x (fp16)
__device__ __align__(16) __half g_Wt[3*DIM*DIM];    // Wq|Wk|Wv (fp16)
__device__ __align__(16) __half g_Wot[DIM*DIM];     // Wo (fp16)
__device__ __align__(16) __half g_q[BHN*SEQ*HD];    // normalized q (fp16)
__device__ __align__(16) __half g_k[BHN*SEQ*HD];    // normalized k (fp16)
__device__ __align__(16) __half g_v[BHN*SEQ*HD];    // v (fp16, NOT pre-scaled)
__device__ __align__(16) float g_gateq[BHN*SEQ];
__device__ __align__(16) float g_gatek[BHN*SEQ];
__device__ __align__(16) __half g_coll[MROWS*DIM];  // collapse (fp16)

// ---------------- helpers ----------------
__device__ __forceinline__ void mma16(float c[4],
                                      uint32_t a0, uint32_t a1, uint32_t a2, uint32_t a3,
                                      uint32_t b0, uint32_t b1) {
    asm volatile(
        "mma.sync.aligned.m16n8k16.row.col.f32.f16.f16.f32 "
        "{%0,%1,%2,%3},{%4,%5,%6,%7},{%8,%9},{%0,%1,%2,%3};"
        : "+f"(c[0]), "+f"(c[1]), "+f"(c[2]), "+f"(c[3])
        : "r"(a0), "r"(a1), "r"(a2), "r"(a3), "r"(b0), "r"(b1));
}
__device__ __forceinline__ void ldsm4(uint32_t r[4], uint32_t addr) {
    asm volatile("ldmatrix.sync.aligned.m8n8.x4.shared.b16 {%0,%1,%2,%3}, [%4];"
                 : "=r"(r[0]), "=r"(r[1]), "=r"(r[2]), "=r"(r[3]) : "r"(addr));
}
__device__ __forceinline__ void ldsm4t(uint32_t r[4], uint32_t addr) {
    asm volatile("ldmatrix.sync.aligned.m8n8.x4.trans.shared.b16 {%0,%1,%2,%3}, [%4];"
                 : "=r"(r[0]), "=r"(r[1]), "=r"(r[2]), "=r"(r[3]) : "r"(addr));
}
__device__ __forceinline__ void cpa16(uint32_t s, const void* g) {
    asm volatile("cp.async.ca.shared.global [%0], [%1], 16;" :: "r"(s), "l"(g) : "memory");
}
__device__ __forceinline__ void cp_commit() { asm volatile("cp.async.commit_group;" ::: "memory"); }
__device__ __forceinline__ void cp_wait0()  { asm volatile("cp.async.wait_group 0;" ::: "memory"); }
__device__ __forceinline__ uint32_t s2u(const void* p) {
    return (uint32_t)__cvta_generic_to_shared(p);
}
__device__ __forceinline__ float frcp(float x) {
    float r; asm("rcp.approx.f32 %0, %1;" : "=f"(r) : "f"(x)); return r;
}

// ---------------- weight fp16 pre-convert ----------------
__global__ void __launch_bounds__(256) cvtW_kernel(const float* __restrict__ Wq,
                                                   const float* __restrict__ Wk,
                                                   const float* __restrict__ Wv,
                                                   const float* __restrict__ Wo) {
    int m = blockIdx.y;
    const float* s = (m == 0) ? Wq : (m == 1) ? Wk : (m == 2) ? Wv : Wo;
    __half* d = (m == 3) ? g_Wot : (g_Wt + (size_t)m * DIM * DIM);
    int i = (blockIdx.x * 256 + threadIdx.x) * 4;
    float4 v = *(const float4*)(s + i);
    ((__half2*)(d + i))[0] = __floats2half2_rn(v.x, v.y);
    ((__half2*)(d + i))[1] = __floats2half2_rn(v.z, v.w);
}

// ---------------- LayerNorm (emits fp16 x_norm and fp16 raw x) ----------------
__global__ void __launch_bounds__(256) ln_kernel(const float* __restrict__ x,
                                                 const float* __restrict__ w,
                                                 const float* __restrict__ b) {
    int row = blockIdx.x;
    const float4* xr = (const float4*)(x + (size_t)row * DIM);
    float4 v = xr[threadIdx.x];
    float s  = v.x + v.y + v.z + v.w;
    float ss = v.x*v.x + v.y*v.y + v.z*v.z + v.w*v.w;
    #pragma unroll
    for (int o = 16; o > 0; o >>= 1) {
        s  += __shfl_xor_sync(0xffffffffu, s,  o);
        ss += __shfl_xor_sync(0xffffffffu, ss, o);
    }
    __shared__ float rs[8], rss[8];
    int wid = threadIdx.x >> 5, lane = threadIdx.x & 31;
    if (lane == 0) { rs[wid] = s; rss[wid] = ss; }
    __syncthreads();
    if (wid == 0) {
        float a = (lane < 8) ? rs[lane]  : 0.f;
        float c = (lane < 8) ? rss[lane] : 0.f;
        #pragma unroll
        for (int o = 4; o > 0; o >>= 1) {
            a += __shfl_xor_sync(0xffffffffu, a, o);
            c += __shfl_xor_sync(0xffffffffu, c, o);
        }
        if (lane == 0) { rs[0] = a; rss[0] = c; }
    }
    __syncthreads();
    float mu   = rs[0] * (1.0f / DIM);
    float var  = rss[0] * (1.0f / DIM) - mu * mu;
    float rstd = rsqrtf(var + 1e-5f);
    int c0 = threadIdx.x * 4;
    float4 wv = *(const float4*)(w + c0);
    float4 bv = *(const float4*)(b + c0);
    float y0 = (v.x - mu) * rstd * wv.x + bv.x;
    float y1 = (v.y - mu) * rstd * wv.y + bv.y;
    float y2 = (v.z - mu) * rstd * wv.z + bv.z;
    float y3 = (v.w - mu) * rstd * wv.w + bv.w;
    __half* dn = g_xn + (size_t)row * DIM + c0;
    ((__half2*)dn)[0] = __floats2half2_rn(y0, y1);
    ((__half2*)dn)[1] = __floats2half2_rn(y2, y3);
    __half* dt = g_xt + (size_t)row * DIM + c0;
    ((__half2*)dt)[0] = __floats2half2_rn(v.x, v.y);
    ((__half2*)dt)[1] = __floats2half2_rn(v.z, v.w);
}

// ---------------- QKV GEMM (fp16 mma, 128x128x32) + fused l2norm/gates ----------
#define PA 40     // sA pitch (halves)
#define PB 136    // sB pitch (halves)
__global__ void __launch_bounds__(256) gemm_qkv(const float* __restrict__ gqv,
                                                const float* __restrict__ gkv) {
    int mode = blockIdx.z;
    const __half* A = (mode == 2) ? g_xt : g_xn;
    const __half* W = g_Wt + (size_t)mode * DIM * DIM;
    __half* C = (mode == 0) ? g_q : ((mode == 1) ? g_k : g_v);

    __shared__ __half sA[2][128 * PA];
    __shared__ __half sB[2][32 * PB];
    uint32_t sAu = s2u(sA), sBu = s2u(sB);

    int tid = threadIdx.x, lane = tid & 31, wid = tid >> 5;
    int g = lane >> 2, tg = lane & 3;
    int m0  = (wid & 3) * 32;
    int n0b = (wid >> 2) * 64;
    int row0 = blockIdx.y * 128, col0 = blockIdx.x * 128;

    int aRow = tid >> 1, aOff = (tid & 1) * 16;
    int bK = tid >> 3, bN = (tid & 7) * 16;
    const __half* gA = A + (size_t)(row0 + aRow) * DIM + aOff;
    const __half* gB = W + (size_t)bK * DIM + col0 + bN;

    float acc[2][8][4];
    #pragma unroll
    for (int mt = 0; mt < 2; mt++)
        #pragma unroll
        for (int nt = 0; nt < 8; nt++)
            #pragma unroll
            for (int i = 0; i < 4; i++) acc[mt][nt][i] = 0.f;

    auto issue = [&](int it) {
        int k0 = it * 32, buf = it & 1;
        uint32_t da = sAu + (buf * 128 * PA + aRow * PA + aOff) * 2;
        cpa16(da,      gA + k0);
        cpa16(da + 16, gA + k0 + 8);
        uint32_t db = sBu + (buf * 32 * PB + bK * PB + bN) * 2;
        const __half* gb = gB + (size_t)k0 * DIM;
        cpa16(db,      gb);
        cpa16(db + 16, gb + 8);
    };

    int lr = lane & 15, lh = (lane >> 4) * 8;
    issue(0); cp_commit();
    for (int it = 0; it < 32; it++) {
        cp_wait0();
        __syncthreads();
        if (it < 31) { issue(it + 1); cp_commit(); }
        int buf = it & 1;
        uint32_t aB = sAu + buf * (128 * PA * 2);
        uint32_t bB = sBu + buf * (32 * PB * 2);
        #pragma unroll
        for (int ks = 0; ks < 2; ks++) {
            int kk = ks * 16;
            uint32_t aF[2][4];
            #pragma unroll
            for (int mt = 0; mt < 2; mt++)
                ldsm4(aF[mt], aB + ((m0 + mt * 16 + lr) * PA + kk + lh) * 2);
            uint32_t bF[4][4];
            #pragma unroll
            for (int ntp = 0; ntp < 4; ntp++)
                ldsm4t(bF[ntp], bB + ((kk + lr) * PB + n0b + ntp * 16 + lh) * 2);
            #pragma unroll
            for (int mt = 0; mt < 2; mt++)
                #pragma unroll
                for (int ntp = 0; ntp < 4; ntp++) {
                    mma16(acc[mt][ntp*2],   aF[mt][0], aF[mt][1], aF[mt][2], aF[mt][3],
                          bF[ntp][0], bF[ntp][1]);
                    mma16(acc[mt][ntp*2+1], aF[mt][0], aF[mt][1], aF[mt][2], aF[mt][3],
                          bF[ntp][2], bF[ntp][3]);
                }
        }
    }

    // epilogue. Warp n-range = col0+n0b .. +64 = exactly one head.
    int h = (col0 + n0b) >> 6;
    if (mode < 2) {
        const float* gvec = (mode == 0) ? gqv : gkv;
        float* gout = (mode == 0) ? g_gateq : g_gatek;
        float2 gv[8];
        #pragma unroll
        for (int nt = 0; nt < 8; nt++)
            gv[nt] = *(const float2*)(gvec + nt * 8 + 2 * tg);
        #pragma unroll
        for (int mt = 0; mt < 2; mt++) {
            float ss1 = 0.f, ss2 = 0.f, gt1 = 0.f, gt2 = 0.f;
            #pragma unroll
            for (int nt = 0; nt < 8; nt++) {
                ss1 += acc[mt][nt][0]*acc[mt][nt][0] + acc[mt][nt][1]*acc[mt][nt][1];
                ss2 += acc[mt][nt][2]*acc[mt][nt][2] + acc[mt][nt][3]*acc[mt][nt][3];
                gt1 += acc[mt][nt][0]*gv[nt].x + acc[mt][nt][1]*gv[nt].y;
                gt2 += acc[mt][nt][2]*gv[nt].x + acc[mt][nt][3]*gv[nt].y;
            }
            #pragma unroll
            for (int o = 1; o <= 2; o <<= 1) {
                ss1 += __shfl_xor_sync(0xffffffffu, ss1, o);
                ss2 += __shfl_xor_sync(0xffffffffu, ss2, o);
                gt1 += __shfl_xor_sync(0xffffffffu, gt1, o);
                gt2 += __shfl_xor_sync(0xffffffffu, gt2, o);
            }
            float rn1 = 1.0f / fmaxf(sqrtf(ss1), 1e-12f);
            float rn2 = 1.0f / fmaxf(sqrtf(ss2), 1e-12f);
            int r1 = row0 + m0 + mt * 16 + g, r2 = r1 + 8;
            int b1 = r1 >> 11, t1 = r1 & 2047;
            int b2 = r2 >> 11, t2 = r2 & 2047;
            if (tg == 0) {
                gout[(size_t)(b1 * HEADS + h) * SEQ + t1] = gt1 * rn1;
                gout[(size_t)(b2 * HEADS + h) * SEQ + t2] = gt2 * rn2;
            }
            #pragma unroll
            for (int nt = 0; nt < 8; nt++) {
                int d = nt * 8 + 2 * tg;
                *(__half2*)&C[((size_t)(b1 * HEADS + h) * SEQ + t1) * HD + d] =
                    __floats2half2_rn(acc[mt][nt][0] * rn1, acc[mt][nt][1] * rn1);
                *(__half2*)&C[((size_t)(b2 * HEADS + h) * SEQ + t2) * HD + d] =
                    __floats2half2_rn(acc[mt][nt][2] * rn2, acc[mt][nt][3] * rn2);
            }
        }
    } else {
        #pragma unroll
        for (int mt = 0; mt < 2; mt++) {
            int r1 = row0 + m0 + mt * 16 + g, r2 = r1 + 8;
            int b1 = r1 >> 11, t1 = r1 & 2047;
            int b2 = r2 >> 11, t2 = r2 & 2047;
            #pragma unroll
            for (int nt = 0; nt < 8; nt++) {
                int d = nt * 8 + 2 * tg;
                *(__half2*)&C[((size_t)(b1 * HEADS + h) * SEQ + t1) * HD + d] =
                    __floats2half2_rn(acc[mt][nt][0], acc[mt][nt][1]);
                *(__half2*)&C[((size_t)(b2 * HEADS + h) * SEQ + t2) * HD + d] =
                    __floats2half2_rn(acc[mt][nt][2], acc[mt][nt][3]);
            }
        }
    }
}

// ---------------- attention: flash-style, register P, 128q x 64s tiles ----------
// 8 warps, warp = 16 q-rows x full 64 s-cols; P stays in registers (C-frag ->
// A-frag pack). gate_k applied to P from smem table; gate_q in epilogue.
#define ATP 72
#define KTILE (64*ATP)
#define ATT_SMEM (128*ATP*2 + 2*KTILE*2*2 + SEQ*4)  /* 18432+36864+8192 = 63488 B */
__global__ void __launch_bounds__(256, 2) attn_kernel() {
    extern __shared__ __align__(16) char smraw[];
    __half* sQ = (__half*)smraw;                 // 128*ATP halves
    __half* sK = sQ + 128 * ATP;                 // 2*KTILE
    __half* sV = sK + 2 * KTILE;                 // 2*KTILE
    float*  sGk = (float*)(sV + 2 * KTILE);      // SEQ floats
    uint32_t qB = s2u(sQ), kB0 = s2u(sK), vB0 = s2u(sV), gkB = s2u(sGk);

    int bh = blockIdx.y, t0 = blockIdx.x * 128;
    const __half* Q = g_q + ((size_t)bh * SEQ + t0) * HD;
    const __half* K = g_k + (size_t)bh * SEQ * HD;
    const __half* V = g_v + (size_t)bh * SEQ * HD;
    const float* Gk = g_gatek + (size_t)bh * SEQ;

    int tid = threadIdx.x, lane = tid & 31, wid = tid >> 5;
    int g = lane >> 2, tg = lane & 3;
    int m0 = wid * 16;
    int lr = lane & 15, lh = (lane >> 4) * 8;
    int lr8 = ((lane >> 4) << 3) + (lane & 7), lk8 = ((lane >> 3) & 1) * 8;

    // group 0: Q tile + gate_k table + KV tile 0
    #pragma unroll
    for (int f = 0; f < 4; f++) {
        int e = tid + f * 256, r = e >> 3, o = (e & 7) * 8;
        cpa16(qB + (r * ATP + o) * 2, Q + r * HD + o);
    }
    #pragma unroll
    for (int f = 0; f < 2; f++) {
        int c = tid + f * 256;
        cpa16(gkB + c * 16, Gk + c * 4);
    }
    #pragma unroll
    for (int f = 0; f < 2; f++) {
        int e = tid + f * 256, r = e >> 3, o = (e & 7) * 8;
        cpa16(kB0 + (r * ATP + o) * 2, K + r * HD + o);
        cpa16(vB0 + (r * ATP + o) * 2, V + r * HD + o);
    }
    cp_commit();

    uint32_t aQ[4][4];
    float O[8][4];
    #pragma unroll
    for (int nd = 0; nd < 8; nd++)
        #pragma unroll
        for (int i = 0; i < 4; i++) O[nd][i] = 0.f;

    for (int it = 0; it < SEQ / 64; it++) {
        cp_wait0();
        __syncthreads();
        if (it + 1 < SEQ / 64) {
            int s0n = (it + 1) * 64, buf = (it + 1) & 1;
            #pragma unroll
            for (int f = 0; f < 2; f++) {
                int e = tid + f * 256, r = e >> 3, o = (e & 7) * 8;
                cpa16(kB0 + (buf * KTILE + r * ATP + o) * 2, K + (size_t)(s0n + r) * HD + o);
                cpa16(vB0 + (buf * KTILE + r * ATP + o) * 2, V + (size_t)(s0n + r) * HD + o);
            }
            cp_commit();
        }
        if (it == 0) {
            #pragma unroll
            for (int ks = 0; ks < 4; ks++)
                ldsm4(aQ[ks], qB + ((m0 + lr) * ATP + ks * 16 + lh) * 2);
        }
        uint32_t kBa = kB0 + (it & 1) * KTILE * 2;
        uint32_t vBa = vB0 + (it & 1) * KTILE * 2;

        // S = Q @ K^T  (16 x 64 per warp)
        float S[8][4];
        #pragma unroll
        for (int nc = 0; nc < 8; nc++)
            #pragma unroll
            for (int i = 0; i < 4; i++) S[nc][i] = 0.f;
        #pragma unroll
        for (int ks = 0; ks < 4; ks++) {
            int kk = ks * 16;
            #pragma unroll
            for (int np = 0; np < 4; np++) {
                uint32_t bF[4];
                ldsm4(bF, kBa + ((np * 16 + lr8) * ATP + kk + lk8) * 2);
                mma16(S[np*2],   aQ[ks][0], aQ[ks][1], aQ[ks][2], aQ[ks][3], bF[0], bF[1]);
                mma16(S[np*2+1], aQ[ks][0], aQ[ks][1], aQ[ks][2], aQ[ks][3], bF[2], bF[3]);
            }
        }

        // P = sigmoid((S-TH)*SHARP) * gate_k[s], packed straight into A-frags
        uint32_t aP[8][2];
        int sBase = it * 64;
        #pragma unroll
        for (int nc = 0; nc < 8; nc++) {
            float2 gk2 = *(const float2*)&sGk[sBase + nc * 8 + 2 * tg];
            float e0 = __expf(-(S[nc][0] - TH) * SHARP);
            float e1 = __expf(-(S[nc][1] - TH) * SHARP);
            float e2 = __expf(-(S[nc][2] - TH) * SHARP);
            float e3 = __expf(-(S[nc][3] - TH) * SHARP);
            float a0 = 1.f + e0, a1 = 1.f + e1, a2 = 1.f + e2, a3 = 1.f + e3;
            float r01 = frcp(a0 * a1);
            float r23 = frcp(a2 * a3);
            float p0 = a1 * r01 * gk2.x, p1 = a0 * r01 * gk2.y;
            float p2 = a3 * r23 * gk2.x, p3 = a2 * r23 * gk2.y;
            __half2 h0 = __floats2half2_rn(p0, p1);
            __half2 h1 = __floats2half2_rn(p2, p3);
            aP[nc][0] = *(uint32_t*)&h0;
            aP[nc][1] = *(uint32_t*)&h1;
        }

        // O += P @ V
        #pragma unroll
        for (int ks = 0; ks < 4; ks++) {
            int kk = ks * 16;
            #pragma unroll
            for (int nd = 0; nd < 4; nd++) {
                uint32_t bF[4];
                ldsm4t(bF, vBa + ((kk + lr) * ATP + nd * 16 + lh) * 2);
                mma16(O[nd*2],   aP[2*ks][0], aP[2*ks][1], aP[2*ks+1][0], aP[2*ks+1][1],
                      bF[0], bF[1]);
                mma16(O[nd*2+1], aP[2*ks][0], aP[2*ks][1], aP[2*ks+1][0], aP[2*ks+1][1],
                      bF[2], bF[3]);
            }
        }
    }

    // epilogue: * gate_q, fp16 into row-major collapse layout
    int b = bh >> 4, h = bh & 15;
    int t1 = t0 + m0 + g, t2 = t1 + 8;
    float gq1 = g_gateq[(size_t)bh * SEQ + t1];
    float gq2 = g_gateq[(size_t)bh * SEQ + t2];
    #pragma unroll
    for (int od = 0; od < 8; od++) {
        int d = od * 8 + 2 * tg;
        *(__half2*)&g_coll[((size_t)(b * SEQ + t1) * HEADS + h) * HD + d] =
            __floats2half2_rn(O[od][0] * gq1, O[od][1] * gq1);
        *(__half2*)&g_coll[((size_t)(b * SEQ + t2) * HEADS + h) * HD + d] =
            __floats2half2_rn(O[od][2] * gq2, O[od][3] * gq2);
    }
}

// ---------------- output GEMM + bias (fp16 mma, single-sync pipeline) ----------
__global__ void __launch_bounds__(256) gemm_out(const float* __restrict__ bo,
                                                float* __restrict__ out) {
    __shared__ __half sA[2][128 * PA];
    __shared__ __half sB[2][32 * PB];
    uint32_t sAu = s2u(sA), sBu = s2u(sB);

    int tid = threadIdx.x, lane = tid & 31, wid = tid >> 5;
    int g = lane >> 2, tg = lane & 3;
    int m0  = (wid & 3) * 32;
    int n0b = (wid >> 2) * 64;
    int row0 = blockIdx.y * 128, col0 = blockIdx.x * 128;

    int aRow = tid >> 1, aOff = (tid & 1) * 16;
    int bK = tid >> 3, bN = (tid & 7) * 16;
    const __half* gA = g_coll + (size_t)(row0 + aRow) * DIM + aOff;
    const __half* gB = g_Wot + (size_t)bK * DIM + col0 + bN;

    float acc[2][8][4];
    #pragma unroll
    for (int mt = 0; mt < 2; mt++)
        #pragma unroll
        for (int nt = 0; nt < 8; nt++)
            #pragma unroll
            for (int i = 0; i < 4; i++) acc[mt][nt][i] = 0.f;

    auto issue = [&](int it) {
        int k0 = it * 32, buf = it & 1;
        uint32_t da = sAu + (buf * 128 * PA + aRow * PA + aOff) * 2;
        cpa16(da,      gA + k0);
        cpa16(da + 16, gA + k0 + 8);
        uint32_t db = sBu + (buf * 32 * PB + bK * PB + bN) * 2;
        const __half* gb = gB + (size_t)k0 * DIM;
        cpa16(db,      gb);
        cpa16(db + 16, gb + 8);
    };

    int lr = lane & 15, lh = (lane >> 4) * 8;
    issue(0); cp_commit();
    for (int it = 0; it < 32; it++) {
        cp_wait0();
        __syncthreads();
        if (it < 31) { issue(it + 1); cp_commit(); }
        int buf = it & 1;
        uint32_t aB = sAu + buf * (128 * PA * 2);
        uint32_t bB = sBu + buf * (32 * PB * 2);
        #pragma unroll
        for (int ks = 0; ks < 2; ks++) {
            int kk = ks * 16;
            uint32_t aF[2][4];
            #pragma unroll
            for (int mt = 0; mt < 2; mt++)
                ldsm4(aF[mt], aB + ((m0 + mt * 16 + lr) * PA + kk + lh) * 2);
            uint32_t bF[4][4];
            #pragma unroll
            for (int ntp = 0; ntp < 4; ntp++)
                ldsm4t(bF[ntp], bB + ((kk + lr) * PB + n0b + ntp * 16 + lh) * 2);
            #pragma unroll
            for (int mt = 0; mt < 2; mt++)
                #pragma unroll
                for (int ntp = 0; ntp < 4; ntp++) {
                    mma16(acc[mt][ntp*2],   aF[mt][0], aF[mt][1], aF[mt][2], aF[mt][3],
                          bF[ntp][0], bF[ntp][1]);
                    mma16(acc[mt][ntp*2+1], aF[mt][0], aF[mt][1], aF[mt][2], aF[mt][3],
                          bF[ntp][2], bF[ntp][3]);
                }
        }
    }

    #pragma unroll
    for (int mt = 0; mt < 2; mt++) {
        int r1 = row0 + m0 + mt * 16 + g;
        int r2 = r1 + 8;
        #pragma unroll
        for (int nt = 0; nt < 8; nt++) {
            int c = col0 + n0b + nt * 8 + 2 * tg;
            float2 bv = *(const float2*)(bo + c);
            *(float2*)&out[(size_t)r1 * DIM + c] =
                make_float2(acc[mt][nt][0] + bv.x, acc[mt][nt][1] + bv.y);
            *(float2*)&out[(size_t)r2 * DIM + c] =
                make_float2(acc[mt][nt][2] + bv.x, acc[mt][nt][3] + bv.y);
        }
    }
}

// ---------------- launcher ----------------
extern "C" void kernel_launch(void* const* d_in, const int* in_sizes, int n_in,
                              void* d_out, int out_size) {
    const float* x   = (const float*)d_in[0];
    const float* gq  = (const float*)d_in[4];
    const float* gk  = (const float*)d_in[5];
    const float* bo  = (const float*)d_in[7];
    const float* lnw = (const float*)d_in[8];
    const float* lnb = (const float*)d_in[9];
    float* out = (float*)d_out;

    cudaFuncSetAttribute(attn_kernel, cudaFuncAttributeMaxDynamicSharedMemorySize,
                         ATT_SMEM);

    cvtW_kernel<<<dim3(DIM * DIM / 1024, 4), 256>>>((const float*)d_in[1],
                                                    (const float*)d_in[2],
                                                    (const float*)d_in[3],
                                                    (const float*)d_in[6]);
    ln_kernel<<<MROWS, 256>>>(x, lnw, lnb);
    gemm_qkv<<<dim3(8, 32, 3), 256>>>(gq, gk);
    attn_kernel<<<dim3(SEQ / 128, BHN), 256, ATT_SMEM>>>();
    gemm_out<<<dim3(8, 32), 256>>>(bo, out);
}

// round 12
// speedup vs baseline: 6.7330x; 1.0350x over previous
#include <cuda_runtime.h>
#include <cuda_fp16.h>
#include <math.h>
#include <stdint.h>

#define DIM   1024
#define BATCH 2
#define SEQ   2048
#define HEADS 16
#define HD    64
#define MROWS (BATCH*SEQ)   /* 4096 */
#define BHN   (BATCH*HEADS) /* 32 */
#define TH    0.29514f
#define SHARP 15.0f

// ---------------- scratch (device globals: allocation-free) ----------------
__device__ __align__(16) __half g_xn[MROWS*DIM];    // layernormed x (fp16)
__device__ __align__(16) __half g_xt[MROWS*DIM];    // raw x (fp16)
__device__ __align__(16) __half g_Wt[3*DIM*DIM];    // Wq|Wk|Wv (fp16)
__device__ __align__(16) __half g_Wot[DIM*DIM];     // Wo (fp16)
__device__ __align__(16) __half g_q[BHN*SEQ*HD];    // normalized q (fp16)
__device__ __align__(16) __half g_k[BHN*SEQ*HD];    // normalized k (fp16)
__device__ __align__(16) __half g_v[BHN*SEQ*HD];    // v (fp16), scaled by gate_k in scale_v
__device__ __align__(16) float g_gateq[BHN*SEQ];
__device__ __align__(16) float g_gatek[BHN*SEQ];
__device__ __align__(16) __half g_coll[MROWS*DIM];  // collapse (fp16)

// ---------------- helpers ----------------
__device__ __forceinline__ void mma16(float c[4],
                                      uint32_t a0, uint32_t a1, uint32_t a2, uint32_t a3,
                                      uint32_t b0, uint32_t b1) {
    asm volatile(
        "mma.sync.aligned.m16n8k16.row.col.f32.f16.f16.f32 "
        "{%0,%1,%2,%3},{%4,%5,%6,%7},{%8,%9},{%0,%1,%2,%3};"
        : "+f"(c[0]), "+f"(c[1]), "+f"(c[2]), "+f"(c[3])
        : "r"(a0), "r"(a1), "r"(a2), "r"(a3), "r"(b0), "r"(b1));
}
__device__ __forceinline__ void ldsm4(uint32_t r[4], uint32_t addr) {
    asm volatile("ldmatrix.sync.aligned.m8n8.x4.shared.b16 {%0,%1,%2,%3}, [%4];"
                 : "=r"(r[0]), "=r"(r[1]), "=r"(r[2]), "=r"(r[3]) : "r"(addr));
}
__device__ __forceinline__ void ldsm4t(uint32_t r[4], uint32_t addr) {
    asm volatile("ldmatrix.sync.aligned.m8n8.x4.trans.shared.b16 {%0,%1,%2,%3}, [%4];"
                 : "=r"(r[0]), "=r"(r[1]), "=r"(r[2]), "=r"(r[3]) : "r"(addr));
}
__device__ __forceinline__ void cpa16(uint32_t s, const void* g) {
    asm volatile("cp.async.ca.shared.global [%0], [%1], 16;" :: "r"(s), "l"(g) : "memory");
}
__device__ __forceinline__ void cp_commit() { asm volatile("cp.async.commit_group;" ::: "memory"); }
__device__ __forceinline__ void cp_wait0()  { asm volatile("cp.async.wait_group 0;" ::: "memory"); }
__device__ __forceinline__ uint32_t s2u(const void* p) {
    return (uint32_t)__cvta_generic_to_shared(p);
}
__device__ __forceinline__ float frcp(float x) {
    float r; asm("rcp.approx.f32 %0, %1;" : "=f"(r) : "f"(x)); return r;
}
__device__ __forceinline__ float fex2(float x) {
    float r; asm("ex2.approx.f32 %0, %1;" : "=f"(r) : "f"(x)); return r;
}

// ---------------- weight fp16 pre-convert ----------------
__global__ void __launch_bounds__(256) cvtW_kernel(const float* __restrict__ Wq,
                                                   const float* __restrict__ Wk,
                                                   const float* __restrict__ Wv,
                                                   const float* __restrict__ Wo) {
    int m = blockIdx.y;
    const float* s = (m == 0) ? Wq : (m == 1) ? Wk : (m == 2) ? Wv : Wo;
    __half* d = (m == 3) ? g_Wot : (g_Wt + (size_t)m * DIM * DIM);
    int i = (blockIdx.x * 256 + threadIdx.x) * 4;
    float4 v = *(const float4*)(s + i);
    ((__half2*)(d + i))[0] = __floats2half2_rn(v.x, v.y);
    ((__half2*)(d + i))[1] = __floats2half2_rn(v.z, v.w);
}

// ---------------- LayerNorm (emits fp16 x_norm and fp16 raw x) ----------------
__global__ void __launch_bounds__(256) ln_kernel(const float* __restrict__ x,
                                                 const float* __restrict__ w,
                                                 const float* __restrict__ b) {
    int row = blockIdx.x;
    const float4* xr = (const float4*)(x + (size_t)row * DIM);
    float4 v = xr[threadIdx.x];
    float s  = v.x + v.y + v.z + v.w;
    float ss = v.x*v.x + v.y*v.y + v.z*v.z + v.w*v.w;
    #pragma unroll
    for (int o = 16; o > 0; o >>= 1) {
        s  += __shfl_xor_sync(0xffffffffu, s,  o);
        ss += __shfl_xor_sync(0xffffffffu, ss, o);
    }
    __shared__ float rs[8], rss[8];
    int wid = threadIdx.x >> 5, lane = threadIdx.x & 31;
    if (lane == 0) { rs[wid] = s; rss[wid] = ss; }
    __syncthreads();
    if (wid == 0) {
        float a = (lane < 8) ? rs[lane]  : 0.f;
        float c = (lane < 8) ? rss[lane] : 0.f;
        #pragma unroll
        for (int o = 4; o > 0; o >>= 1) {
            a += __shfl_xor_sync(0xffffffffu, a, o);
            c += __shfl_xor_sync(0xffffffffu, c, o);
        }
        if (lane == 0) { rs[0] = a; rss[0] = c; }
    }
    __syncthreads();
    float mu   = rs[0] * (1.0f / DIM);
    float var  = rss[0] * (1.0f / DIM) - mu * mu;
    float rstd = rsqrtf(var + 1e-5f);
    int c0 = threadIdx.x * 4;
    float4 wv = *(const float4*)(w + c0);
    float4 bv = *(const float4*)(b + c0);
    float y0 = (v.x - mu) * rstd * wv.x + bv.x;
    float y1 = (v.y - mu) * rstd * wv.y + bv.y;
    float y2 = (v.z - mu) * rstd * wv.z + bv.z;
    float y3 = (v.w - mu) * rstd * wv.w + bv.w;
    __half* dn = g_xn + (size_t)row * DIM + c0;
    ((__half2*)dn)[0] = __floats2half2_rn(y0, y1);
    ((__half2*)dn)[1] = __floats2half2_rn(y2, y3);
    __half* dt = g_xt + (size_t)row * DIM + c0;
    ((__half2*)dt)[0] = __floats2half2_rn(v.x, v.y);
    ((__half2*)dt)[1] = __floats2half2_rn(v.z, v.w);
}

// ---------------- QKV GEMM (fp16 mma, 128x128x32) + fused l2norm/gates ----------
#define PA 40     // sA pitch (halves)
#define PB 136    // sB pitch (halves)
__global__ void __launch_bounds__(256) gemm_qkv(const float* __restrict__ gqv,
                                                const float* __restrict__ gkv) {
    int mode = blockIdx.z;
    const __half* A = (mode == 2) ? g_xt : g_xn;
    const __half* W = g_Wt + (size_t)mode * DIM * DIM;
    __half* C = (mode == 0) ? g_q : ((mode == 1) ? g_k : g_v);

    __shared__ __half sA[2][128 * PA];
    __shared__ __half sB[2][32 * PB];
    uint32_t sAu = s2u(sA), sBu = s2u(sB);

    int tid = threadIdx.x, lane = tid & 31, wid = tid >> 5;
    int g = lane >> 2, tg = lane & 3;
    int m0  = (wid & 3) * 32;
    int n0b = (wid >> 2) * 64;
    int row0 = blockIdx.y * 128, col0 = blockIdx.x * 128;

    int aRow = tid >> 1, aOff = (tid & 1) * 16;
    int bK = tid >> 3, bN = (tid & 7) * 16;
    const __half* gA = A + (size_t)(row0 + aRow) * DIM + aOff;
    const __half* gB = W + (size_t)bK * DIM + col0 + bN;

    float acc[2][8][4];
    #pragma unroll
    for (int mt = 0; mt < 2; mt++)
        #pragma unroll
        for (int nt = 0; nt < 8; nt++)
            #pragma unroll
            for (int i = 0; i < 4; i++) acc[mt][nt][i] = 0.f;

    auto issue = [&](int it) {
        int k0 = it * 32, buf = it & 1;
        uint32_t da = sAu + (buf * 128 * PA + aRow * PA + aOff) * 2;
        cpa16(da,      gA + k0);
        cpa16(da + 16, gA + k0 + 8);
        uint32_t db = sBu + (buf * 32 * PB + bK * PB + bN) * 2;
        const __half* gb = gB + (size_t)k0 * DIM;
        cpa16(db,      gb);
        cpa16(db + 16, gb + 8);
    };

    int lr = lane & 15, lh = (lane >> 4) * 8;
    issue(0); cp_commit();
    for (int it = 0; it < 32; it++) {
        cp_wait0();
        __syncthreads();
        if (it < 31) { issue(it + 1); cp_commit(); }
        int buf = it & 1;
        uint32_t aB = sAu + buf * (128 * PA * 2);
        uint32_t bB = sBu + buf * (32 * PB * 2);
        #pragma unroll
        for (int ks = 0; ks < 2; ks++) {
            int kk = ks * 16;
            uint32_t aF[2][4];
            #pragma unroll
            for (int mt = 0; mt < 2; mt++)
                ldsm4(aF[mt], aB + ((m0 + mt * 16 + lr) * PA + kk + lh) * 2);
            uint32_t bF[4][4];
            #pragma unroll
            for (int ntp = 0; ntp < 4; ntp++)
                ldsm4t(bF[ntp], bB + ((kk + lr) * PB + n0b + ntp * 16 + lh) * 2);
            #pragma unroll
            for (int mt = 0; mt < 2; mt++)
                #pragma unroll
                for (int ntp = 0; ntp < 4; ntp++) {
                    mma16(acc[mt][ntp*2],   aF[mt][0], aF[mt][1], aF[mt][2], aF[mt][3],
                          bF[ntp][0], bF[ntp][1]);
                    mma16(acc[mt][ntp*2+1], aF[mt][0], aF[mt][1], aF[mt][2], aF[mt][3],
                          bF[ntp][2], bF[ntp][3]);
                }
        }
    }

    // epilogue. Warp n-range = col0+n0b .. +64 = exactly one head.
    int h = (col0 + n0b) >> 6;
    if (mode < 2) {
        const float* gvec = (mode == 0) ? gqv : gkv;
        float* gout = (mode == 0) ? g_gateq : g_gatek;
        float2 gv[8];
        #pragma unroll
        for (int nt = 0; nt < 8; nt++)
            gv[nt] = *(const float2*)(gvec + nt * 8 + 2 * tg);
        #pragma unroll
        for (int mt = 0; mt < 2; mt++) {
            float ss1 = 0.f, ss2 = 0.f, gt1 = 0.f, gt2 = 0.f;
            #pragma unroll
            for (int nt = 0; nt < 8; nt++) {
                ss1 += acc[mt][nt][0]*acc[mt][nt][0] + acc[mt][nt][1]*acc[mt][nt][1];
                ss2 += acc[mt][nt][2]*acc[mt][nt][2] + acc[mt][nt][3]*acc[mt][nt][3];
                gt1 += acc[mt][nt][0]*gv[nt].x + acc[mt][nt][1]*gv[nt].y;
                gt2 += acc[mt][nt][2]*gv[nt].x + acc[mt][nt][3]*gv[nt].y;
            }
            #pragma unroll
            for (int o = 1; o <= 2; o <<= 1) {
                ss1 += __shfl_xor_sync(0xffffffffu, ss1, o);
                ss2 += __shfl_xor_sync(0xffffffffu, ss2, o);
                gt1 += __shfl_xor_sync(0xffffffffu, gt1, o);
                gt2 += __shfl_xor_sync(0xffffffffu, gt2, o);
            }
            float rn1 = 1.0f / fmaxf(sqrtf(ss1), 1e-12f);
            float rn2 = 1.0f / fmaxf(sqrtf(ss2), 1e-12f);
            int r1 = row0 + m0 + mt * 16 + g, r2 = r1 + 8;
            int b1 = r1 >> 11, t1 = r1 & 2047;
            int b2 = r2 >> 11, t2 = r2 & 2047;
            if (tg == 0) {
                gout[(size_t)(b1 * HEADS + h) * SEQ + t1] = gt1 * rn1;
                gout[(size_t)(b2 * HEADS + h) * SEQ + t2] = gt2 * rn2;
            }
            #pragma unroll
            for (int nt = 0; nt < 8; nt++) {
                int d = nt * 8 + 2 * tg;
                *(__half2*)&C[((size_t)(b1 * HEADS + h) * SEQ + t1) * HD + d] =
                    __floats2half2_rn(acc[mt][nt][0] * rn1, acc[mt][nt][1] * rn1);
                *(__half2*)&C[((size_t)(b2 * HEADS + h) * SEQ + t2) * HD + d] =
                    __floats2half2_rn(acc[mt][nt][2] * rn2, acc[mt][nt][3] * rn2);
            }
        }
    } else {
        #pragma unroll
        for (int mt = 0; mt < 2; mt++) {
            int r1 = row0 + m0 + mt * 16 + g, r2 = r1 + 8;
            int b1 = r1 >> 11, t1 = r1 & 2047;
            int b2 = r2 >> 11, t2 = r2 & 2047;
            #pragma unroll
            for (int nt = 0; nt < 8; nt++) {
                int d = nt * 8 + 2 * tg;
                *(__half2*)&C[((size_t)(b1 * HEADS + h) * SEQ + t1) * HD + d] =
                    __floats2half2_rn(acc[mt][nt][0], acc[mt][nt][1]);
                *(__half2*)&C[((size_t)(b2 * HEADS + h) * SEQ + t2) * HD + d] =
                    __floats2half2_rn(acc[mt][nt][2], acc[mt][nt][3]);
            }
        }
    }
}

// ---------------- V pre-scale by gate_k ----------------
// g_v[row][*] *= g_gatek[row]; row = bh*SEQ+s. uint4 = 8 halves; 8 uint4/row.
__global__ void __launch_bounds__(256) scale_v_kernel() {
    int i = blockIdx.x * 256 + threadIdx.x;     // uint4 index, total BHN*SEQ*8
    int row = i >> 3;
    __half2 gk = __float2half2_rn(g_gatek[row]);
    uint4* p = (uint4*)g_v + i;
    uint4 v = *p;
    __half2* h = (__half2*)&v;
    h[0] = __hmul2(h[0], gk);
    h[1] = __hmul2(h[1], gk);
    h[2] = __hmul2(h[2], gk);
    h[3] = __hmul2(h[3], gk);
    *p = v;
}

// ---------------- attention: flash-style, register P, per-chunk interleave ------
// 8 warps, warp = 16 q-rows x 64 s-cols per tile; S->sigmoid->PV per 16-col chunk.
#define ATP 72
#define KTILE (64*ATP)
#define ATT_SMEM ((128*ATP + 2*KTILE*2) * 2)   /* (9216+36864)*2 = 55296+... bytes */
__global__ void __launch_bounds__(256, 2) attn_kernel() {
    extern __shared__ __align__(16) char smraw[];
    __half* sQ = (__half*)smraw;                 // 128*ATP halves
    __half* sK = sQ + 128 * ATP;                 // 2 tiles
    __half* sV = sK + 2 * KTILE;                 // 2 tiles
    uint32_t qB = s2u(sQ), kB0 = s2u(sK), vB0 = s2u(sV);

    int bh = blockIdx.y, t0 = blockIdx.x * 128;
    const __half* Q = g_q + ((size_t)bh * SEQ + t0) * HD;
    const __half* K = g_k + (size_t)bh * SEQ * HD;
    const __half* V = g_v + (size_t)bh * SEQ * HD;

    int tid = threadIdx.x, lane = tid & 31, wid = tid >> 5;
    int g = lane >> 2, tg = lane & 3;
    int m0 = wid * 16;
    int lr = lane & 15, lh = (lane >> 4) * 8;
    int lr8 = ((lane >> 4) << 3) + (lane & 7), lk8 = ((lane >> 3) & 1) * 8;

    const float C1 = -SHARP * 1.4426950408889634f;
    const float C0 =  TH * SHARP * 1.4426950408889634f;

    // group 0: Q tile + KV tile 0
    #pragma unroll
    for (int f = 0; f < 4; f++) {
        int e = tid + f * 256, r = e >> 3, o = (e & 7) * 8;
        cpa16(qB + (r * ATP + o) * 2, Q + r * HD + o);
    }
    #pragma unroll
    for (int f = 0; f < 2; f++) {
        int e = tid + f * 256, r = e >> 3, o = (e & 7) * 8;
        cpa16(kB0 + (r * ATP + o) * 2, K + r * HD + o);
        cpa16(vB0 + (r * ATP + o) * 2, V + r * HD + o);
    }
    cp_commit();

    uint32_t aQ[4][4];
    float O[8][4];
    #pragma unroll
    for (int nd = 0; nd < 8; nd++)
        #pragma unroll
        for (int i = 0; i < 4; i++) O[nd][i] = 0.f;

    for (int it = 0; it < SEQ / 64; it++) {
        cp_wait0();
        __syncthreads();
        if (it + 1 < SEQ / 64) {
            int s0n = (it + 1) * 64, buf = (it + 1) & 1;
            #pragma unroll
            for (int f = 0; f < 2; f++) {
                int e = tid + f * 256, r = e >> 3, o = (e & 7) * 8;
                cpa16(kB0 + (buf * KTILE + r * ATP + o) * 2, K + (size_t)(s0n + r) * HD + o);
                cpa16(vB0 + (buf * KTILE + r * ATP + o) * 2, V + (size_t)(s0n + r) * HD + o);
            }
            cp_commit();
        }
        if (it == 0) {
            #pragma unroll
            for (int ks = 0; ks < 4; ks++)
                ldsm4(aQ[ks], qB + ((m0 + lr) * ATP + ks * 16 + lh) * 2);
        }
        uint32_t kBa = kB0 + (it & 1) * KTILE * 2;
        uint32_t vBa = vB0 + (it & 1) * KTILE * 2;

        // per 16-column s-chunk: S mma -> sigmoid -> PV mma (interleaved pipes)
        #pragma unroll
        for (int np = 0; np < 4; np++) {
            float S0[4] = {0.f, 0.f, 0.f, 0.f};
            float S1[4] = {0.f, 0.f, 0.f, 0.f};
            #pragma unroll
            for (int kd = 0; kd < 4; kd++) {
                uint32_t bF[4];
                ldsm4(bF, kBa + ((np * 16 + lr8) * ATP + kd * 16 + lk8) * 2);
                mma16(S0, aQ[kd][0], aQ[kd][1], aQ[kd][2], aQ[kd][3], bF[0], bF[1]);
                mma16(S1, aQ[kd][0], aQ[kd][1], aQ[kd][2], aQ[kd][3], bF[2], bF[3]);
            }
            // sigmoid: e = ex2(S*C1 + C0); p = 1/(1+e) via paired rcp
            uint32_t aP0[2], aP1[2];
            {
                float a0 = 1.f + fex2(fmaf(S0[0], C1, C0));
                float a1 = 1.f + fex2(fmaf(S0[1], C1, C0));
                float a2 = 1.f + fex2(fmaf(S0[2], C1, C0));
                float a3 = 1.f + fex2(fmaf(S0[3], C1, C0));
                float r01 = frcp(a0 * a1), r23 = frcp(a2 * a3);
                __half2 h0 = __floats2half2_rn(a1 * r01, a0 * r01);
                __half2 h1 = __floats2half2_rn(a3 * r23, a2 * r23);
                aP0[0] = *(uint32_t*)&h0; aP0[1] = *(uint32_t*)&h1;
            }
            {
                float a0 = 1.f + fex2(fmaf(S1[0], C1, C0));
                float a1 = 1.f + fex2(fmaf(S1[1], C1, C0));
                float a2 = 1.f + fex2(fmaf(S1[2], C1, C0));
                float a3 = 1.f + fex2(fmaf(S1[3], C1, C0));
                float r01 = frcp(a0 * a1), r23 = frcp(a2 * a3);
                __half2 h0 = __floats2half2_rn(a1 * r01, a0 * r01);
                __half2 h1 = __floats2half2_rn(a3 * r23, a2 * r23);
                aP1[0] = *(uint32_t*)&h0; aP1[1] = *(uint32_t*)&h1;
            }
            // O += P(:, np-chunk) @ V(np-chunk, :)
            #pragma unroll
            for (int nd = 0; nd < 4; nd++) {
                uint32_t vF[4];
                ldsm4t(vF, vBa + ((np * 16 + lr) * ATP + nd * 16 + lh) * 2);
                mma16(O[nd*2],   aP0[0], aP0[1], aP1[0], aP1[1], vF[0], vF[1]);
                mma16(O[nd*2+1], aP0[0], aP0[1], aP1[0], aP1[1], vF[2], vF[3]);
            }
        }
    }

    // epilogue: * gate_q, fp16 into row-major collapse layout
    int b = bh >> 4, h = bh & 15;
    int t1 = t0 + m0 + g, t2 = t1 + 8;
    float gq1 = g_gateq[(size_t)bh * SEQ + t1];
    float gq2 = g_gateq[(size_t)bh * SEQ + t2];
    #pragma unroll
    for (int od = 0; od < 8; od++) {
        int d = od * 8 + 2 * tg;
        *(__half2*)&g_coll[((size_t)(b * SEQ + t1) * HEADS + h) * HD + d] =
            __floats2half2_rn(O[od][0] * gq1, O[od][1] * gq1);
        *(__half2*)&g_coll[((size_t)(b * SEQ + t2) * HEADS + h) * HD + d] =
            __floats2half2_rn(O[od][2] * gq2, O[od][3] * gq2);
    }
}

// ---------------- output GEMM + bias (fp16 mma, single-sync pipeline) ----------
__global__ void __launch_bounds__(256) gemm_out(const float* __restrict__ bo,
                                                float* __restrict__ out) {
    __shared__ __half sA[2][128 * PA];
    __shared__ __half sB[2][32 * PB];
    uint32_t sAu = s2u(sA), sBu = s2u(sB);

    int tid = threadIdx.x, lane = tid & 31, wid = tid >> 5;
    int g = lane >> 2, tg = lane & 3;
    int m0  = (wid & 3) * 32;
    int n0b = (wid >> 2) * 64;
    int row0 = blockIdx.y * 128, col0 = blockIdx.x * 128;

    int aRow = tid >> 1, aOff = (tid & 1) * 16;
    int bK = tid >> 3, bN = (tid & 7) * 16;
    const __half* gA = g_coll + (size_t)(row0 + aRow) * DIM + aOff;
    const __half* gB = g_Wot + (size_t)bK * DIM + col0 + bN;

    float acc[2][8][4];
    #pragma unroll
    for (int mt = 0; mt < 2; mt++)
        #pragma unroll
        for (int nt = 0; nt < 8; nt++)
            #pragma unroll
            for (int i = 0; i < 4; i++) acc[mt][nt][i] = 0.f;

    auto issue = [&](int it) {
        int k0 = it * 32, buf = it & 1;
        uint32_t da = sAu + (buf * 128 * PA + aRow * PA + aOff) * 2;
        cpa16(da,      gA + k0);
        cpa16(da + 16, gA + k0 + 8);
        uint32_t db = sBu + (buf * 32 * PB + bK * PB + bN) * 2;
        const __half* gb = gB + (size_t)k0 * DIM;
        cpa16(db,      gb);
        cpa16(db + 16, gb + 8);
    };

    int lr = lane & 15, lh = (lane >> 4) * 8;
    issue(0); cp_commit();
    for (int it = 0; it < 32; it++) {
        cp_wait0();
        __syncthreads();
        if (it < 31) { issue(it + 1); cp_commit(); }
        int buf = it & 1;
        uint32_t aB = sAu + buf * (128 * PA * 2);
        uint32_t bB = sBu + buf * (32 * PB * 2);
        #pragma unroll
        for (int ks = 0; ks < 2; ks++) {
            int kk = ks * 16;
            uint32_t aF[2][4];
            #pragma unroll
            for (int mt = 0; mt < 2; mt++)
                ldsm4(aF[mt], aB + ((m0 + mt * 16 + lr) * PA + kk + lh) * 2);
            uint32_t bF[4][4];
            #pragma unroll
            for (int ntp = 0; ntp < 4; ntp++)
                ldsm4t(bF[ntp], bB + ((kk + lr) * PB + n0b + ntp * 16 + lh) * 2);
            #pragma unroll
            for (int mt = 0; mt < 2; mt++)
                #pragma unroll
                for (int ntp = 0; ntp < 4; ntp++) {
                    mma16(acc[mt][ntp*2],   aF[mt][0], aF[mt][1], aF[mt][2], aF[mt][3],
                          bF[ntp][0], bF[ntp][1]);
                    mma16(acc[mt][ntp*2+1], aF[mt][0], aF[mt][1], aF[mt][2], aF[mt][3],
                          bF[ntp][2], bF[ntp][3]);
                }
        }
    }

    #pragma unroll
    for (int mt = 0; mt < 2; mt++) {
        int r1 = row0 + m0 + mt * 16 + g;
        int r2 = r1 + 8;
        #pragma unroll
        for (int nt = 0; nt < 8; nt++) {
            int c = col0 + n0b + nt * 8 + 2 * tg;
            float2 bv = *(const float2*)(bo + c);
            *(float2*)&out[(size_t)r1 * DIM + c] =
                make_float2(acc[mt][nt][0] + bv.x, acc[mt][nt][1] + bv.y);
            *(float2*)&out[(size_t)r2 * DIM + c] =
                make_float2(acc[mt][nt][2] + bv.x, acc[mt][nt][3] + bv.y);
        }
    }
}

// ---------------- launcher ----------------
extern "C" void kernel_launch(void* const* d_in, const int* in_sizes, int n_in,
                              void* d_out, int out_size) {
    const float* x   = (const float*)d_in[0];
    const float* gq  = (const float*)d_in[4];
    const float* gk  = (const float*)d_in[5];
    const float* bo  = (const float*)d_in[7];
    const float* lnw = (const float*)d_in[8];
    const float* lnb = (const float*)d_in[9];
    float* out = (float*)d_out;

    cudaFuncSetAttribute(attn_kernel, cudaFuncAttributeMaxDynamicSharedMemorySize,
                         ATT_SMEM);

    cvtW_kernel<<<dim3(DIM * DIM / 1024, 4), 256>>>((const float*)d_in[1],
                                                    (const float*)d_in[2],
                                                    (const float*)d_in[3],
                                                    (const float*)d_in[6]);
    ln_kernel<<<MROWS, 256>>>(x, lnw, lnb);
    gemm_qkv<<<dim3(8, 32, 3), 256>>>(gq, gk);
    scale_v_kernel<<<(BHN * SEQ * 8) / 256, 256>>>();
    attn_kernel<<<dim3(SEQ / 128, BHN), 256, ATT_SMEM>>>();
    gemm_out<<<dim3(8, 32), 256>>>(bo, out);
}

// round 14
// speedup vs baseline: 6.8803x; 1.0219x over previous
#include <cuda_runtime.h>
#include <cuda_fp16.h>
#include <math.h>
#include <stdint.h>

#define DIM   1024
#define BATCH 2
#define SEQ   2048
#define HEADS 16
#define HD    64
#define MROWS (BATCH*SEQ)   /* 4096 */
#define BHN   (BATCH*HEADS) /* 32 */
#define TH    0.29514f
#define SHARP 15.0f

// ---------------- scratch (device globals: allocation-free) ----------------
__device__ __align__(16) __half g_xn[MROWS*DIM];    // layernormed x (fp16)
__device__ __align__(16) __half g_xt[MROWS*DIM];    // raw x (fp16)
__device__ __align__(16) __half g_Wt[3*DIM*DIM];    // Wq|Wk|Wv (fp16, [k][n])
__device__ __align__(16) __half g_Wot[DIM*DIM];     // Wo (fp16, [k][n])
__device__ __align__(16) __half g_q[BHN*SEQ*HD];    // normalized q (fp16)
__device__ __align__(16) __half g_k[BHN*SEQ*HD];    // normalized k (fp16)
__device__ __align__(16) __half g_v[BHN*SEQ*HD];    // v (fp16), scaled by gate_k in scale_v
__device__ __align__(16) float g_gateq[BHN*SEQ];
__device__ __align__(16) float g_gatek[BHN*SEQ];
__device__ __align__(16) __half g_coll[MROWS*DIM];  // collapse (fp16)

// ---------------- helpers ----------------
__device__ __forceinline__ void mma16(float c[4],
                                      uint32_t a0, uint32_t a1, uint32_t a2, uint32_t a3,
                                      uint32_t b0, uint32_t b1) {
    asm volatile(
        "mma.sync.aligned.m16n8k16.row.col.f32.f16.f16.f32 "
        "{%0,%1,%2,%3},{%4,%5,%6,%7},{%8,%9},{%0,%1,%2,%3};"
        : "+f"(c[0]), "+f"(c[1]), "+f"(c[2]), "+f"(c[3])
        : "r"(a0), "r"(a1), "r"(a2), "r"(a3), "r"(b0), "r"(b1));
}
__device__ __forceinline__ void ldsm4(uint32_t r[4], uint32_t addr) {
    asm volatile("ldmatrix.sync.aligned.m8n8.x4.shared.b16 {%0,%1,%2,%3}, [%4];"
                 : "=r"(r[0]), "=r"(r[1]), "=r"(r[2]), "=r"(r[3]) : "r"(addr));
}
__device__ __forceinline__ void ldsm4t(uint32_t r[4], uint32_t addr) {
    asm volatile("ldmatrix.sync.aligned.m8n8.x4.trans.shared.b16 {%0,%1,%2,%3}, [%4];"
                 : "=r"(r[0]), "=r"(r[1]), "=r"(r[2]), "=r"(r[3]) : "r"(addr));
}
__device__ __forceinline__ void cpa16(uint32_t s, const void* g) {
    asm volatile("cp.async.ca.shared.global [%0], [%1], 16;" :: "r"(s), "l"(g) : "memory");
}
__device__ __forceinline__ void cp_commit() { asm volatile("cp.async.commit_group;" ::: "memory"); }
__device__ __forceinline__ void cp_wait1()  { asm volatile("cp.async.wait_group 1;" ::: "memory"); }
__device__ __forceinline__ void cp_wait0()  { asm volatile("cp.async.wait_group 0;" ::: "memory"); }
__device__ __forceinline__ uint32_t s2u(const void* p) {
    return (uint32_t)__cvta_generic_to_shared(p);
}
__device__ __forceinline__ float frcp(float x) {
    float r; asm("rcp.approx.f32 %0, %1;" : "=f"(r) : "f"(x)); return r;
}
__device__ __forceinline__ float fex2(float x) {
    float r; asm("ex2.approx.f32 %0, %1;" : "=f"(r) : "f"(x)); return r;
}

// ---------------- weight fp16 pre-convert ----------------
__global__ void __launch_bounds__(256) cvtW_kernel(const float* __restrict__ Wq,
                                                   const float* __restrict__ Wk,
                                                   const float* __restrict__ Wv,
                                                   const float* __restrict__ Wo) {
    int m = blockIdx.y;
    const float* s = (m == 0) ? Wq : (m == 1) ? Wk : (m == 2) ? Wv : Wo;
    __half* d = (m == 3) ? g_Wot : (g_Wt + (size_t)m * DIM * DIM);
    int i = (blockIdx.x * 256 + threadIdx.x) * 4;
    float4 v = *(const float4*)(s + i);
    ((__half2*)(d + i))[0] = __floats2half2_rn(v.x, v.y);
    ((__half2*)(d + i))[1] = __floats2half2_rn(v.z, v.w);
}

// ---------------- LayerNorm (emits fp16 x_norm and fp16 raw x) ----------------
__global__ void __launch_bounds__(256) ln_kernel(const float* __restrict__ x,
                                                 const float* __restrict__ w,
                                                 const float* __restrict__ b) {
    int row = blockIdx.x;
    const float4* xr = (const float4*)(x + (size_t)row * DIM);
    float4 v = xr[threadIdx.x];
    float s  = v.x + v.y + v.z + v.w;
    float ss = v.x*v.x + v.y*v.y + v.z*v.z + v.w*v.w;
    #pragma unroll
    for (int o = 16; o > 0; o >>= 1) {
        s  += __shfl_xor_sync(0xffffffffu, s,  o);
        ss += __shfl_xor_sync(0xffffffffu, ss, o);
    }
    __shared__ float rs[8], rss[8];
    int wid = threadIdx.x >> 5, lane = threadIdx.x & 31;
    if (lane == 0) { rs[wid] = s; rss[wid] = ss; }
    __syncthreads();
    if (wid == 0) {
        float a = (lane < 8) ? rs[lane]  : 0.f;
        float c = (lane < 8) ? rss[lane] : 0.f;
        #pragma unroll
        for (int o = 4; o > 0; o >>= 1) {
            a += __shfl_xor_sync(0xffffffffu, a, o);
            c += __shfl_xor_sync(0xffffffffu, c, o);
        }
        if (lane == 0) { rs[0] = a; rss[0] = c; }
    }
    __syncthreads();
    float mu   = rs[0] * (1.0f / DIM);
    float var  = rss[0] * (1.0f / DIM) - mu * mu;
    float rstd = rsqrtf(var + 1e-5f);
    int c0 = threadIdx.x * 4;
    float4 wv = *(const float4*)(w + c0);
    float4 bv = *(const float4*)(b + c0);
    float y0 = (v.x - mu) * rstd * wv.x + bv.x;
    float y1 = (v.y - mu) * rstd * wv.y + bv.y;
    float y2 = (v.z - mu) * rstd * wv.z + bv.z;
    float y3 = (v.w - mu) * rstd * wv.w + bv.w;
    __half* dn = g_xn + (size_t)row * DIM + c0;
    ((__half2*)dn)[0] = __floats2half2_rn(y0, y1);
    ((__half2*)dn)[1] = __floats2half2_rn(y2, y3);
    __half* dt = g_xt + (size_t)row * DIM + c0;
    ((__half2*)dt)[0] = __floats2half2_rn(v.x, v.y);
    ((__half2*)dt)[1] = __floats2half2_rn(v.z, v.w);
}

// ---------------- QKV GEMM (fp16 mma, 128x128x32, 3-stage cp.async) -------------
#define PA 40     // sA pitch (halves)
#define PB 136    // sB pitch (halves)
#define GQ_STG (128*PA + 32*PB)        /* halves per stage: 5120 + 4352 = 9472  */
#define GQ_SMEM (3*GQ_STG*2)           /* 56832 B                                */
__global__ void __launch_bounds__(256) gemm_qkv(const float* __restrict__ gqv,
                                                const float* __restrict__ gkv) {
    int mode = blockIdx.z;
    const __half* A = (mode == 2) ? g_xt : g_xn;
    const __half* W = g_Wt + (size_t)mode * DIM * DIM;
    __half* C = (mode == 0) ? g_q : ((mode == 1) ? g_k : g_v);

    extern __shared__ __align__(16) __half gsm[];
    uint32_t smem_u = s2u(gsm);

    int tid = threadIdx.x, lane = tid & 31, wid = tid >> 5;
    int g = lane >> 2, tg = lane & 3;
    int m0  = (wid & 3) * 32;
    int n0b = (wid >> 2) * 64;
    int row0 = blockIdx.y * 128, col0 = blockIdx.x * 128;

    int aRow = tid >> 1, aOff = (tid & 1) * 16;
    int bK = tid >> 3, bN = (tid & 7) * 16;
    const __half* gA = A + (size_t)(row0 + aRow) * DIM + aOff;
    const __half* gB = W + (size_t)bK * DIM + col0 + bN;

    float acc[2][8][4];
    #pragma unroll
    for (int mt = 0; mt < 2; mt++)
        #pragma unroll
        for (int nt = 0; nt < 8; nt++)
            #pragma unroll
            for (int i = 0; i < 4; i++) acc[mt][nt][i] = 0.f;

    auto issue = [&](int s) {
        int k0 = s * 32, buf = s % 3;
        uint32_t da = smem_u + (buf * GQ_STG + aRow * PA + aOff) * 2;
        cpa16(da,      gA + k0);
        cpa16(da + 16, gA + k0 + 8);
        uint32_t db = smem_u + (buf * GQ_STG + 128 * PA + bK * PB + bN) * 2;
        const __half* gb = gB + (size_t)k0 * DIM;
        cpa16(db,      gb);
        cpa16(db + 16, gb + 8);
    };

    int lr = lane & 15, lh = (lane >> 4) * 8;
    issue(0); cp_commit();
    issue(1); cp_commit();
    for (int it = 0; it < 32; it++) {
        if (it < 31) cp_wait1(); else cp_wait0();
        __syncthreads();
        if (it + 2 < 32) { issue(it + 2); cp_commit(); }
        int buf = it % 3;
        uint32_t aB = smem_u + buf * GQ_STG * 2;
        uint32_t bB = aB + 128 * PA * 2;
        #pragma unroll
        for (int ks = 0; ks < 2; ks++) {
            int kk = ks * 16;
            uint32_t aF[2][4];
            #pragma unroll
            for (int mt = 0; mt < 2; mt++)
                ldsm4(aF[mt], aB + ((m0 + mt * 16 + lr) * PA + kk + lh) * 2);
            uint32_t bF[4][4];
            #pragma unroll
            for (int ntp = 0; ntp < 4; ntp++)
                ldsm4t(bF[ntp], bB + ((kk + lr) * PB + n0b + ntp * 16 + lh) * 2);
            #pragma unroll
            for (int mt = 0; mt < 2; mt++)
                #pragma unroll
                for (int ntp = 0; ntp < 4; ntp++) {
                    mma16(acc[mt][ntp*2],   aF[mt][0], aF[mt][1], aF[mt][2], aF[mt][3],
                          bF[ntp][0], bF[ntp][1]);
                    mma16(acc[mt][ntp*2+1], aF[mt][0], aF[mt][1], aF[mt][2], aF[mt][3],
                          bF[ntp][2], bF[ntp][3]);
                }
        }
    }

    // epilogue. Warp n-range = col0+n0b .. +64 = exactly one head.
    int h = (col0 + n0b) >> 6;
    if (mode < 2) {
        const float* gvec = (mode == 0) ? gqv : gkv;
        float* gout = (mode == 0) ? g_gateq : g_gatek;
        float2 gv[8];
        #pragma unroll
        for (int nt = 0; nt < 8; nt++)
            gv[nt] = *(const float2*)(gvec + nt * 8 + 2 * tg);
        #pragma unroll
        for (int mt = 0; mt < 2; mt++) {
            float ss1 = 0.f, ss2 = 0.f, gt1 = 0.f, gt2 = 0.f;
            #pragma unroll
            for (int nt = 0; nt < 8; nt++) {
                ss1 += acc[mt][nt][0]*acc[mt][nt][0] + acc[mt][nt][1]*acc[mt][nt][1];
                ss2 += acc[mt][nt][2]*acc[mt][nt][2] + acc[mt][nt][3]*acc[mt][nt][3];
                gt1 += acc[mt][nt][0]*gv[nt].x + acc[mt][nt][1]*gv[nt].y;
                gt2 += acc[mt][nt][2]*gv[nt].x + acc[mt][nt][3]*gv[nt].y;
            }
            #pragma unroll
            for (int o = 1; o <= 2; o <<= 1) {
                ss1 += __shfl_xor_sync(0xffffffffu, ss1, o);
                ss2 += __shfl_xor_sync(0xffffffffu, ss2, o);
                gt1 += __shfl_xor_sync(0xffffffffu, gt1, o);
                gt2 += __shfl_xor_sync(0xffffffffu, gt2, o);
            }
            float rn1 = 1.0f / fmaxf(sqrtf(ss1), 1e-12f);
            float rn2 = 1.0f / fmaxf(sqrtf(ss2), 1e-12f);
            int r1 = row0 + m0 + mt * 16 + g, r2 = r1 + 8;
            int b1 = r1 >> 11, t1 = r1 & 2047;
            int b2 = r2 >> 11, t2 = r2 & 2047;
            if (tg == 0) {
                gout[(size_t)(b1 * HEADS + h) * SEQ + t1] = gt1 * rn1;
                gout[(size_t)(b2 * HEADS + h) * SEQ + t2] = gt2 * rn2;
            }
            #pragma unroll
            for (int nt = 0; nt < 8; nt++) {
                int d = nt * 8 + 2 * tg;
                *(__half2*)&C[((size_t)(b1 * HEADS + h) * SEQ + t1) * HD + d] =
                    __floats2half2_rn(acc[mt][nt][0] * rn1, acc[mt][nt][1] * rn1);
                *(__half2*)&C[((size_t)(b2 * HEADS + h) * SEQ + t2) * HD + d] =
                    __floats2half2_rn(acc[mt][nt][2] * rn2, acc[mt][nt][3] * rn2);
            }
        }
    } else {
        #pragma unroll
        for (int mt = 0; mt < 2; mt++) {
            int r1 = row0 + m0 + mt * 16 + g, r2 = r1 + 8;
            int b1 = r1 >> 11, t1 = r1 & 2047;
            int b2 = r2 >> 11, t2 = r2 & 2047;
            #pragma unroll
            for (int nt = 0; nt < 8; nt++) {
                int d = nt * 8 + 2 * tg;
                *(__half2*)&C[((size_t)(b1 * HEADS + h) * SEQ + t1) * HD + d] =
                    __floats2half2_rn(acc[mt][nt][0], acc[mt][nt][1]);
                *(__half2*)&C[((size_t)(b2 * HEADS + h) * SEQ + t2) * HD + d] =
                    __floats2half2_rn(acc[mt][nt][2], acc[mt][nt][3]);
            }
        }
    }
}

// ---------------- V pre-scale by gate_k ----------------
__global__ void __launch_bounds__(256) scale_v_kernel() {
    int i = blockIdx.x * 256 + threadIdx.x;     // uint4 index, total BHN*SEQ*8
    int row = i >> 3;
    __half2 gk = __float2half2_rn(g_gatek[row]);
    uint4* p = (uint4*)g_v + i;
    uint4 v = *p;
    __half2* h = (__half2*)&v;
    h[0] = __hmul2(h[0], gk);
    h[1] = __hmul2(h[1], gk);
    h[2] = __hmul2(h[2], gk);
    h[3] = __hmul2(h[3], gk);
    *p = v;
}

// ---------------- attention: flash-style, register P, per-chunk interleave ------
#define ATP 72
#define KTILE (64*ATP)
#define ATT_SMEM ((128*ATP + 2*KTILE*2) * 2)
__global__ void __launch_bounds__(256, 2) attn_kernel() {
    extern __shared__ __align__(16) char smraw[];
    __half* sQ = (__half*)smraw;
    __half* sK = sQ + 128 * ATP;
    __half* sV = sK + 2 * KTILE;
    uint32_t qB = s2u(sQ), kB0 = s2u(sK), vB0 = s2u(sV);

    int bh = blockIdx.y, t0 = blockIdx.x * 128;
    const __half* Q = g_q + ((size_t)bh * SEQ + t0) * HD;
    const __half* K = g_k + (size_t)bh * SEQ * HD;
    const __half* V = g_v + (size_t)bh * SEQ * HD;

    int tid = threadIdx.x, lane = tid & 31, wid = tid >> 5;
    int g = lane >> 2, tg = lane & 3;
    int m0 = wid * 16;
    int lr = lane & 15, lh = (lane >> 4) * 8;
    int lr8 = ((lane >> 4) << 3) + (lane & 7), lk8 = ((lane >> 3) & 1) * 8;

    const float C1 = -SHARP * 1.4426950408889634f;
    const float C0 =  TH * SHARP * 1.4426950408889634f;

    #pragma unroll
    for (int f = 0; f < 4; f++) {
        int e = tid + f * 256, r = e >> 3, o = (e & 7) * 8;
        cpa16(qB + (r * ATP + o) * 2, Q + r * HD + o);
    }
    #pragma unroll
    for (int f = 0; f < 2; f++) {
        int e = tid + f * 256, r = e >> 3, o = (e & 7) * 8;
        cpa16(kB0 + (r * ATP + o) * 2, K + r * HD + o);
        cpa16(vB0 + (r * ATP + o) * 2, V + r * HD + o);
    }
    cp_commit();

    uint32_t aQ[4][4];
    float O[8][4];
    #pragma unroll
    for (int nd = 0; nd < 8; nd++)
        #pragma unroll
        for (int i = 0; i < 4; i++) O[nd][i] = 0.f;

    for (int it = 0; it < SEQ / 64; it++) {
        cp_wait0();
        __syncthreads();
        if (it + 1 < SEQ / 64) {
            int s0n = (it + 1) * 64, buf = (it + 1) & 1;
            #pragma unroll
            for (int f = 0; f < 2; f++) {
                int e = tid + f * 256, r = e >> 3, o = (e & 7) * 8;
                cpa16(kB0 + (buf * KTILE + r * ATP + o) * 2, K + (size_t)(s0n + r) * HD + o);
                cpa16(vB0 + (buf * KTILE + r * ATP + o) * 2, V + (size_t)(s0n + r) * HD + o);
            }
            cp_commit();
        }
        if (it == 0) {
            #pragma unroll
            for (int ks = 0; ks < 4; ks++)
                ldsm4(aQ[ks], qB + ((m0 + lr) * ATP + ks * 16 + lh) * 2);
        }
        uint32_t kBa = kB0 + (it & 1) * KTILE * 2;
        uint32_t vBa = vB0 + (it & 1) * KTILE * 2;

        #pragma unroll
        for (int np = 0; np < 4; np++) {
            float S0[4] = {0.f, 0.f, 0.f, 0.f};
            float S1[4] = {0.f, 0.f, 0.f, 0.f};
            #pragma unroll
            for (int kd = 0; kd < 4; kd++) {
                uint32_t bF[4];
                ldsm4(bF, kBa + ((np * 16 + lr8) * ATP + kd * 16 + lk8) * 2);
                mma16(S0, aQ[kd][0], aQ[kd][1], aQ[kd][2], aQ[kd][3], bF[0], bF[1]);
                mma16(S1, aQ[kd][0], aQ[kd][1], aQ[kd][2], aQ[kd][3], bF[2], bF[3]);
            }
            // sigmoid: e = ex2(S*C1 + C0); p = 1/(1+e); ONE rcp per 4 elements
            uint32_t aP0[2], aP1[2];
            {
                float a0 = 1.f + fex2(fmaf(S0[0], C1, C0));
                float a1 = 1.f + fex2(fmaf(S0[1], C1, C0));
                float a2 = 1.f + fex2(fmaf(S0[2], C1, C0));
                float a3 = 1.f + fex2(fmaf(S0[3], C1, C0));
                float a01 = a0 * a1, a23 = a2 * a3;
                float r = frcp(a01 * a23);
                float r01 = a23 * r, r23 = a01 * r;
                __half2 h0 = __floats2half2_rn(a1 * r01, a0 * r01);
                __half2 h1 = __floats2half2_rn(a3 * r23, a2 * r23);
                aP0[0] = *(uint32_t*)&h0; aP0[1] = *(uint32_t*)&h1;
            }
            {
                float a0 = 1.f + fex2(fmaf(S1[0], C1, C0));
                float a1 = 1.f + fex2(fmaf(S1[1], C1, C0));
                float a2 = 1.f + fex2(fmaf(S1[2], C1, C0));
                float a3 = 1.f + fex2(fmaf(S1[3], C1, C0));
                float a01 = a0 * a1, a23 = a2 * a3;
                float r = frcp(a01 * a23);
                float r01 = a23 * r, r23 = a01 * r;
                __half2 h0 = __floats2half2_rn(a1 * r01, a0 * r01);
                __half2 h1 = __floats2half2_rn(a3 * r23, a2 * r23);
                aP1[0] = *(uint32_t*)&h0; aP1[1] = *(uint32_t*)&h1;
            }
            #pragma unroll
            for (int nd = 0; nd < 4; nd++) {
                uint32_t vF[4];
                ldsm4t(vF, vBa + ((np * 16 + lr) * ATP + nd * 16 + lh) * 2);
                mma16(O[nd*2],   aP0[0], aP0[1], aP1[0], aP1[1], vF[0], vF[1]);
                mma16(O[nd*2+1], aP0[0], aP0[1], aP1[0], aP1[1], vF[2], vF[3]);
            }
        }
    }

    int b = bh >> 4, h = bh & 15;
    int t1 = t0 + m0 + g, t2 = t1 + 8;
    float gq1 = g_gateq[(size_t)bh * SEQ + t1];
    float gq2 = g_gateq[(size_t)bh * SEQ + t2];
    #pragma unroll
    for (int od = 0; od < 8; od++) {
        int d = od * 8 + 2 * tg;
        *(__half2*)&g_coll[((size_t)(b * SEQ + t1) * HEADS + h) * HD + d] =
            __floats2half2_rn(O[od][0] * gq1, O[od][1] * gq1);
        *(__half2*)&g_coll[((size_t)(b * SEQ + t2) * HEADS + h) * HD + d] =
            __floats2half2_rn(O[od][2] * gq2, O[od][3] * gq2);
    }
}

// ---------------- output GEMM + bias (fp16 mma, 3-stage cp.async) ---------------
__global__ void __launch_bounds__(256) gemm_out(const float* __restrict__ bo,
                                                float* __restrict__ out) {
    extern __shared__ __align__(16) __half gsm[];
    uint32_t smem_u = s2u(gsm);

    int tid = threadIdx.x, lane = tid & 31, wid = tid >> 5;
    int g = lane >> 2, tg = lane & 3;
    int m0  = (wid & 3) * 32;
    int n0b = (wid >> 2) * 64;
    int row0 = blockIdx.y * 128, col0 = blockIdx.x * 128;

    int aRow = tid >> 1, aOff = (tid & 1) * 16;
    int bK = tid >> 3, bN = (tid & 7) * 16;
    const __half* gA = g_coll + (size_t)(row0 + aRow) * DIM + aOff;
    const __half* gB = g_Wot + (size_t)bK * DIM + col0 + bN;

    float acc[2][8][4];
    #pragma unroll
    for (int mt = 0; mt < 2; mt++)
        #pragma unroll
        for (int nt = 0; nt < 8; nt++)
            #pragma unroll
            for (int i = 0; i < 4; i++) acc[mt][nt][i] = 0.f;

    auto issue = [&](int s) {
        int k0 = s * 32, buf = s % 3;
        uint32_t da = smem_u + (buf * GQ_STG + aRow * PA + aOff) * 2;
        cpa16(da,      gA + k0);
        cpa16(da + 16, gA + k0 + 8);
        uint32_t db = smem_u + (buf * GQ_STG + 128 * PA + bK * PB + bN) * 2;
        const __half* gb = gB + (size_t)k0 * DIM;
        cpa16(db,      gb);
        cpa16(db + 16, gb + 8);
    };

    int lr = lane & 15, lh = (lane >> 4) * 8;
    issue(0); cp_commit();
    issue(1); cp_commit();
    for (int it = 0; it < 32; it++) {
        if (it < 31) cp_wait1(); else cp_wait0();
        __syncthreads();
        if (it + 2 < 32) { issue(it + 2); cp_commit(); }
        int buf = it % 3;
        uint32_t aB = smem_u + buf * GQ_STG * 2;
        uint32_t bB = aB + 128 * PA * 2;
        #pragma unroll
        for (int ks = 0; ks < 2; ks++) {
            int kk = ks * 16;
            uint32_t aF[2][4];
            #pragma unroll
            for (int mt = 0; mt < 2; mt++)
                ldsm4(aF[mt], aB + ((m0 + mt * 16 + lr) * PA + kk + lh) * 2);
            uint32_t bF[4][4];
            #pragma unroll
            for (int ntp = 0; ntp < 4; ntp++)
                ldsm4t(bF[ntp], bB + ((kk + lr) * PB + n0b + ntp * 16 + lh) * 2);
            #pragma unroll
            for (int mt = 0; mt < 2; mt++)
                #pragma unroll
                for (int ntp = 0; ntp < 4; ntp++) {
                    mma16(acc[mt][ntp*2],   aF[mt][0], aF[mt][1], aF[mt][2], aF[mt][3],
                          bF[ntp][0], bF[ntp][1]);
                    mma16(acc[mt][ntp*2+1], aF[mt][0], aF[mt][1], aF[mt][2], aF[mt][3],
                          bF[ntp][2], bF[ntp][3]);
                }
        }
    }

    #pragma unroll
    for (int mt = 0; mt < 2; mt++) {
        int r1 = row0 + m0 + mt * 16 + g;
        int r2 = r1 + 8;
        #pragma unroll
        for (int nt = 0; nt < 8; nt++) {
            int c = col0 + n0b + nt * 8 + 2 * tg;
            float2 bv = *(const float2*)(bo + c);
            *(float2*)&out[(size_t)r1 * DIM + c] =
                make_float2(acc[mt][nt][0] + bv.x, acc[mt][nt][1] + bv.y);
            *(float2*)&out[(size_t)r2 * DIM + c] =
                make_float2(acc[mt][nt][2] + bv.x, acc[mt][nt][3] + bv.y);
        }
    }
}

// ---------------- launcher ----------------
extern "C" void kernel_launch(void* const* d_in, const int* in_sizes, int n_in,
                              void* d_out, int out_size) {
    const float* x   = (const float*)d_in[0];
    const float* gq  = (const float*)d_in[4];
    const float* gk  = (const float*)d_in[5];
    const float* bo  = (const float*)d_in[7];
    const float* lnw = (const float*)d_in[8];
    const float* lnb = (const float*)d_in[9];
    float* out = (float*)d_out;

    cudaFuncSetAttribute(attn_kernel, cudaFuncAttributeMaxDynamicSharedMemorySize,
                         ATT_SMEM);
    cudaFuncSetAttribute(gemm_qkv, cudaFuncAttributeMaxDynamicSharedMemorySize,
                         GQ_SMEM);
    cudaFuncSetAttribute(gemm_out, cudaFuncAttributeMaxDynamicSharedMemorySize,
                         GQ_SMEM);

    cvtW_kernel<<<dim3(DIM * DIM / 1024, 4), 256>>>((const float*)d_in[1],
                                                    (const float*)d_in[2],
                                                    (const float*)d_in[3],
                                                    (const float*)d_in[6]);
    ln_kernel<<<MROWS, 256>>>(x, lnw, lnb);
    gemm_qkv<<<dim3(8, 32, 3), 256, GQ_SMEM>>>(gq, gk);
    scale_v_kernel<<<(BHN * SEQ * 8) / 256, 256>>>();
    attn_kernel<<<dim3(SEQ / 128, BHN), 256, ATT_SMEM>>>();
    gemm_out<<<dim3(8, 32), 256, GQ_SMEM>>>(bo, out);
}

// round 16
// speedup vs baseline: 7.2281x; 1.0505x over previous
#include <cuda_runtime.h>
#include <cuda_fp16.h>
#include <math.h>
#include <stdint.h>

#define DIM   1024
#define BATCH 2
#define SEQ   2048
#define HEADS 16
#define HD    64
#define MROWS (BATCH*SEQ)   /* 4096 */
#define BHN   (BATCH*HEADS) /* 32 */
#define TH    0.29514f
#define SHARP 15.0f

// ---------------- scratch (device globals: allocation-free) ----------------
__device__ __align__(16) __half g_xn[MROWS*DIM];    // layernormed x (fp16)
__device__ __align__(16) __half g_xt[MROWS*DIM];    // raw x (fp16)
__device__ __align__(16) __half g_Wt[3*DIM*DIM];    // Wq|Wk|Wv (fp16, [k][n])
__device__ __align__(16) __half g_Wot[DIM*DIM];     // Wo (fp16, [k][n])
__device__ __align__(16) __half g_q[BHN*SEQ*HD];    // normalized q (fp16)
__device__ __align__(16) __half g_k[BHN*SEQ*HD];    // normalized k (fp16)
__device__ __align__(16) __half g_v[BHN*SEQ*HD];    // v (fp16), scaled by gate_k in scale_v
__device__ __align__(16) float g_gateq[BHN*SEQ];
__device__ __align__(16) float g_gatek[BHN*SEQ];
__device__ __align__(16) __half g_coll[MROWS*DIM];  // collapse (fp16)

// ---------------- helpers ----------------
__device__ __forceinline__ void mma16(float c[4],
                                      uint32_t a0, uint32_t a1, uint32_t a2, uint32_t a3,
                                      uint32_t b0, uint32_t b1) {
    asm volatile(
        "mma.sync.aligned.m16n8k16.row.col.f32.f16.f16.f32 "
        "{%0,%1,%2,%3},{%4,%5,%6,%7},{%8,%9},{%0,%1,%2,%3};"
        : "+f"(c[0]), "+f"(c[1]), "+f"(c[2]), "+f"(c[3])
        : "r"(a0), "r"(a1), "r"(a2), "r"(a3), "r"(b0), "r"(b1));
}
__device__ __forceinline__ void ldsm4(uint32_t r[4], uint32_t addr) {
    asm volatile("ldmatrix.sync.aligned.m8n8.x4.shared.b16 {%0,%1,%2,%3}, [%4];"
                 : "=r"(r[0]), "=r"(r[1]), "=r"(r[2]), "=r"(r[3]) : "r"(addr));
}
__device__ __forceinline__ void ldsm4t(uint32_t r[4], uint32_t addr) {
    asm volatile("ldmatrix.sync.aligned.m8n8.x4.trans.shared.b16 {%0,%1,%2,%3}, [%4];"
                 : "=r"(r[0]), "=r"(r[1]), "=r"(r[2]), "=r"(r[3]) : "r"(addr));
}
__device__ __forceinline__ void cpa16(uint32_t s, const void* g) {
    asm volatile("cp.async.ca.shared.global [%0], [%1], 16;" :: "r"(s), "l"(g) : "memory");
}
__device__ __forceinline__ void cp_commit() { asm volatile("cp.async.commit_group;" ::: "memory"); }
__device__ __forceinline__ void cp_wait1()  { asm volatile("cp.async.wait_group 1;" ::: "memory"); }
__device__ __forceinline__ void cp_wait0()  { asm volatile("cp.async.wait_group 0;" ::: "memory"); }
__device__ __forceinline__ uint32_t s2u(const void* p) {
    return (uint32_t)__cvta_generic_to_shared(p);
}
__device__ __forceinline__ float frcp(float x) {
    float r; asm("rcp.approx.f32 %0, %1;" : "=f"(r) : "f"(x)); return r;
}
__device__ __forceinline__ float fex2(float x) {
    float r; asm("ex2.approx.f32 %0, %1;" : "=f"(r) : "f"(x)); return r;
}

// ---------------- weight fp16 pre-convert ----------------
__global__ void __launch_bounds__(256) cvtW_kernel(const float* __restrict__ Wq,
                                                   const float* __restrict__ Wk,
                                                   const float* __restrict__ Wv,
                                                   const float* __restrict__ Wo) {
    int m = blockIdx.y;
    const float* s = (m == 0) ? Wq : (m == 1) ? Wk : (m == 2) ? Wv : Wo;
    __half* d = (m == 3) ? g_Wot : (g_Wt + (size_t)m * DIM * DIM);
    int i = (blockIdx.x * 256 + threadIdx.x) * 4;
    float4 v = *(const float4*)(s + i);
    ((__half2*)(d + i))[0] = __floats2half2_rn(v.x, v.y);
    ((__half2*)(d + i))[1] = __floats2half2_rn(v.z, v.w);
}

// ---------------- LayerNorm (emits fp16 x_norm and fp16 raw x) ----------------
__global__ void __launch_bounds__(256) ln_kernel(const float* __restrict__ x,
                                                 const float* __restrict__ w,
                                                 const float* __restrict__ b) {
    int row = blockIdx.x;
    const float4* xr = (const float4*)(x + (size_t)row * DIM);
    float4 v = xr[threadIdx.x];
    float s  = v.x + v.y + v.z + v.w;
    float ss = v.x*v.x + v.y*v.y + v.z*v.z + v.w*v.w;
    #pragma unroll
    for (int o = 16; o > 0; o >>= 1) {
        s  += __shfl_xor_sync(0xffffffffu, s,  o);
        ss += __shfl_xor_sync(0xffffffffu, ss, o);
    }
    __shared__ float rs[8], rss[8];
    int wid = threadIdx.x >> 5, lane = threadIdx.x & 31;
    if (lane == 0) { rs[wid] = s; rss[wid] = ss; }
    __syncthreads();
    if (wid == 0) {
        float a = (lane < 8) ? rs[lane]  : 0.f;
        float c = (lane < 8) ? rss[lane] : 0.f;
        #pragma unroll
        for (int o = 4; o > 0; o >>= 1) {
            a += __shfl_xor_sync(0xffffffffu, a, o);
            c += __shfl_xor_sync(0xffffffffu, c, o);
        }
        if (lane == 0) { rs[0] = a; rss[0] = c; }
    }
    __syncthreads();
    float mu   = rs[0] * (1.0f / DIM);
    float var  = rss[0] * (1.0f / DIM) - mu * mu;
    float rstd = rsqrtf(var + 1e-5f);
    int c0 = threadIdx.x * 4;
    float4 wv = *(const float4*)(w + c0);
    float4 bv = *(const float4*)(b + c0);
    float y0 = (v.x - mu) * rstd * wv.x + bv.x;
    float y1 = (v.y - mu) * rstd * wv.y + bv.y;
    float y2 = (v.z - mu) * rstd * wv.z + bv.z;
    float y3 = (v.w - mu) * rstd * wv.w + bv.w;
    __half* dn = g_xn + (size_t)row * DIM + c0;
    ((__half2*)dn)[0] = __floats2half2_rn(y0, y1);
    ((__half2*)dn)[1] = __floats2half2_rn(y2, y3);
    __half* dt = g_xt + (size_t)row * DIM + c0;
    ((__half2*)dt)[0] = __floats2half2_rn(v.x, v.y);
    ((__half2*)dt)[1] = __floats2half2_rn(v.z, v.w);
}

// ---------------- QKV GEMM (fp16 mma, 128x128x32, 3-stage cp.async) -------------
#define PA 40     // sA pitch (halves)
#define PB 136    // sB pitch (halves)
#define GQ_STG (128*PA + 32*PB)        /* halves per stage: 5120 + 4352 = 9472  */
#define GQ_SMEM (3*GQ_STG*2)           /* 56832 B                                */
__global__ void __launch_bounds__(256) gemm_qkv(const float* __restrict__ gqv,
                                                const float* __restrict__ gkv) {
    int mode = blockIdx.z;
    const __half* A = (mode == 2) ? g_xt : g_xn;
    const __half* W = g_Wt + (size_t)mode * DIM * DIM;
    __half* C = (mode == 0) ? g_q : ((mode == 1) ? g_k : g_v);

    extern __shared__ __align__(16) __half gsm[];
    uint32_t smem_u = s2u(gsm);

    int tid = threadIdx.x, lane = tid & 31, wid = tid >> 5;
    int g = lane >> 2, tg = lane & 3;
    int m0  = (wid & 3) * 32;
    int n0b = (wid >> 2) * 64;
    int row0 = blockIdx.y * 128, col0 = blockIdx.x * 128;

    int aRow = tid >> 1, aOff = (tid & 1) * 16;
    int bK = tid >> 3, bN = (tid & 7) * 16;
    const __half* gA = A + (size_t)(row0 + aRow) * DIM + aOff;
    const __half* gB = W + (size_t)bK * DIM + col0 + bN;

    float acc[2][8][4];
    #pragma unroll
    for (int mt = 0; mt < 2; mt++)
        #pragma unroll
        for (int nt = 0; nt < 8; nt++)
            #pragma unroll
            for (int i = 0; i < 4; i++) acc[mt][nt][i] = 0.f;

    auto issue = [&](int s) {
        int k0 = s * 32, buf = s % 3;
        uint32_t da = smem_u + (buf * GQ_STG + aRow * PA + aOff) * 2;
        cpa16(da,      gA + k0);
        cpa16(da + 16, gA + k0 + 8);
        uint32_t db = smem_u + (buf * GQ_STG + 128 * PA + bK * PB + bN) * 2;
        const __half* gb = gB + (size_t)k0 * DIM;
        cpa16(db,      gb);
        cpa16(db + 16, gb + 8);
    };

    int lr = lane & 15, lh = (lane >> 4) * 8;
    issue(0); cp_commit();
    issue(1); cp_commit();
    for (int it = 0; it < 32; it++) {
        if (it < 31) cp_wait1(); else cp_wait0();
        __syncthreads();
        if (it + 2 < 32) { issue(it + 2); cp_commit(); }
        int buf = it % 3;
        uint32_t aB = smem_u + buf * GQ_STG * 2;
        uint32_t bB = aB + 128 * PA * 2;
        #pragma unroll
        for (int ks = 0; ks < 2; ks++) {
            int kk = ks * 16;
            uint32_t aF[2][4];
            #pragma unroll
            for (int mt = 0; mt < 2; mt++)
                ldsm4(aF[mt], aB + ((m0 + mt * 16 + lr) * PA + kk + lh) * 2);
            uint32_t bF[4][4];
            #pragma unroll
            for (int ntp = 0; ntp < 4; ntp++)
                ldsm4t(bF[ntp], bB + ((kk + lr) * PB + n0b + ntp * 16 + lh) * 2);
            #pragma unroll
            for (int mt = 0; mt < 2; mt++)
                #pragma unroll
                for (int ntp = 0; ntp < 4; ntp++) {
                    mma16(acc[mt][ntp*2],   aF[mt][0], aF[mt][1], aF[mt][2], aF[mt][3],
                          bF[ntp][0], bF[ntp][1]);
                    mma16(acc[mt][ntp*2+1], aF[mt][0], aF[mt][1], aF[mt][2], aF[mt][3],
                          bF[ntp][2], bF[ntp][3]);
                }
        }
    }

    // epilogue. Warp n-range = col0+n0b .. +64 = exactly one head.
    int h = (col0 + n0b) >> 6;
    if (mode < 2) {
        const float* gvec = (mode == 0) ? gqv : gkv;
        float* gout = (mode == 0) ? g_gateq : g_gatek;
        float2 gv[8];
        #pragma unroll
        for (int nt = 0; nt < 8; nt++)
            gv[nt] = *(const float2*)(gvec + nt * 8 + 2 * tg);
        #pragma unroll
        for (int mt = 0; mt < 2; mt++) {
            float ss1 = 0.f, ss2 = 0.f, gt1 = 0.f, gt2 = 0.f;
            #pragma unroll
            for (int nt = 0; nt < 8; nt++) {
                ss1 += acc[mt][nt][0]*acc[mt][nt][0] + acc[mt][nt][1]*acc[mt][nt][1];
                ss2 += acc[mt][nt][2]*acc[mt][nt][2] + acc[mt][nt][3]*acc[mt][nt][3];
                gt1 += acc[mt][nt][0]*gv[nt].x + acc[mt][nt][1]*gv[nt].y;
                gt2 += acc[mt][nt][2]*gv[nt].x + acc[mt][nt][3]*gv[nt].y;
            }
            #pragma unroll
            for (int o = 1; o <= 2; o <<= 1) {
                ss1 += __shfl_xor_sync(0xffffffffu, ss1, o);
                ss2 += __shfl_xor_sync(0xffffffffu, ss2, o);
                gt1 += __shfl_xor_sync(0xffffffffu, gt1, o);
                gt2 += __shfl_xor_sync(0xffffffffu, gt2, o);
            }
            float rn1 = 1.0f / fmaxf(sqrtf(ss1), 1e-12f);
            float rn2 = 1.0f / fmaxf(sqrtf(ss2), 1e-12f);
            int r1 = row0 + m0 + mt * 16 + g, r2 = r1 + 8;
            int b1 = r1 >> 11, t1 = r1 & 2047;
            int b2 = r2 >> 11, t2 = r2 & 2047;
            if (tg == 0) {
                gout[(size_t)(b1 * HEADS + h) * SEQ + t1] = gt1 * rn1;
                gout[(size_t)(b2 * HEADS + h) * SEQ + t2] = gt2 * rn2;
            }
            #pragma unroll
            for (int nt = 0; nt < 8; nt++) {
                int d = nt * 8 + 2 * tg;
                *(__half2*)&C[((size_t)(b1 * HEADS + h) * SEQ + t1) * HD + d] =
                    __floats2half2_rn(acc[mt][nt][0] * rn1, acc[mt][nt][1] * rn1);
                *(__half2*)&C[((size_t)(b2 * HEADS + h) * SEQ + t2) * HD + d] =
                    __floats2half2_rn(acc[mt][nt][2] * rn2, acc[mt][nt][3] * rn2);
            }
        }
    } else {
        #pragma unroll
        for (int mt = 0; mt < 2; mt++) {
            int r1 = row0 + m0 + mt * 16 + g, r2 = r1 + 8;
            int b1 = r1 >> 11, t1 = r1 & 2047;
            int b2 = r2 >> 11, t2 = r2 & 2047;
            #pragma unroll
            for (int nt = 0; nt < 8; nt++) {
                int d = nt * 8 + 2 * tg;
                *(__half2*)&C[((size_t)(b1 * HEADS + h) * SEQ + t1) * HD + d] =
                    __floats2half2_rn(acc[mt][nt][0], acc[mt][nt][1]);
                *(__half2*)&C[((size_t)(b2 * HEADS + h) * SEQ + t2) * HD + d] =
                    __floats2half2_rn(acc[mt][nt][2], acc[mt][nt][3]);
            }
        }
    }
}

// ---------------- V pre-scale by gate_k ----------------
__global__ void __launch_bounds__(256) scale_v_kernel() {
    int i = blockIdx.x * 256 + threadIdx.x;     // uint4 index, total BHN*SEQ*8
    int row = i >> 3;
    __half2 gk = __float2half2_rn(g_gatek[row]);
    uint4* p = (uint4*)g_v + i;
    uint4 v = *p;
    __half2* h = (__half2*)&v;
    h[0] = __hmul2(h[0], gk);
    h[1] = __hmul2(h[1], gk);
    h[2] = __hmul2(h[2], gk);
    h[3] = __hmul2(h[3], gk);
    *p = v;
}

// ---------------- attention: flash-style, register P, 64q x 64s, 4 CTAs/SM ------
// 4 warps, warp = 16 q-rows x full 64 s-cols; per-16-col-chunk interleave.
#define ATP 72
#define KTILE (64*ATP)   /* halves per 64-row K or V tile */
#define ATT_SMEM ((64*ATP + 4*KTILE) * 2)   /* (4608+18432)*2 = 46080 B */
__global__ void __launch_bounds__(128, 4) attn_kernel() {
    extern __shared__ __align__(16) char smraw[];
    __half* sQ = (__half*)smraw;           // 64*ATP halves
    __half* sK = sQ + 64 * ATP;            // 2 tiles
    __half* sV = sK + 2 * KTILE;           // 2 tiles
    uint32_t qB = s2u(sQ), kB0 = s2u(sK), vB0 = s2u(sV);

    int bh = blockIdx.y, t0 = blockIdx.x * 64;
    const __half* Q = g_q + ((size_t)bh * SEQ + t0) * HD;
    const __half* K = g_k + (size_t)bh * SEQ * HD;
    const __half* V = g_v + (size_t)bh * SEQ * HD;

    int tid = threadIdx.x, lane = tid & 31, wid = tid >> 5;
    int g = lane >> 2, tg = lane & 3;
    int m0 = wid * 16;
    int lr = lane & 15, lh = (lane >> 4) * 8;
    int lr8 = ((lane >> 4) << 3) + (lane & 7), lk8 = ((lane >> 3) & 1) * 8;

    const float C1 = -SHARP * 1.4426950408889634f;
    const float C0 =  TH * SHARP * 1.4426950408889634f;

    // group 0: Q tile (64 rows) + KV tile 0
    #pragma unroll
    for (int f = 0; f < 4; f++) {
        int e = tid + f * 128, r = e >> 3, o = (e & 7) * 8;
        cpa16(qB + (r * ATP + o) * 2, Q + r * HD + o);
    }
    #pragma unroll
    for (int f = 0; f < 4; f++) {
        int e = tid + f * 128, r = e >> 3, o = (e & 7) * 8;
        cpa16(kB0 + (r * ATP + o) * 2, K + r * HD + o);
        cpa16(vB0 + (r * ATP + o) * 2, V + r * HD + o);
    }
    cp_commit();

    uint32_t aQ[4][4];
    float O[8][4];
    #pragma unroll
    for (int nd = 0; nd < 8; nd++)
        #pragma unroll
        for (int i = 0; i < 4; i++) O[nd][i] = 0.f;

    for (int it = 0; it < SEQ / 64; it++) {
        cp_wait0();
        __syncthreads();
        if (it + 1 < SEQ / 64) {
            int s0n = (it + 1) * 64, buf = (it + 1) & 1;
            #pragma unroll
            for (int f = 0; f < 4; f++) {
                int e = tid + f * 128, r = e >> 3, o = (e & 7) * 8;
                cpa16(kB0 + (buf * KTILE + r * ATP + o) * 2, K + (size_t)(s0n + r) * HD + o);
                cpa16(vB0 + (buf * KTILE + r * ATP + o) * 2, V + (size_t)(s0n + r) * HD + o);
            }
            cp_commit();
        }
        if (it == 0) {
            #pragma unroll
            for (int ks = 0; ks < 4; ks++)
                ldsm4(aQ[ks], qB + ((m0 + lr) * ATP + ks * 16 + lh) * 2);
        }
        uint32_t kBa = kB0 + (it & 1) * KTILE * 2;
        uint32_t vBa = vB0 + (it & 1) * KTILE * 2;

        #pragma unroll
        for (int np = 0; np < 4; np++) {
            float S0[4] = {0.f, 0.f, 0.f, 0.f};
            float S1[4] = {0.f, 0.f, 0.f, 0.f};
            #pragma unroll
            for (int kd = 0; kd < 4; kd++) {
                uint32_t bF[4];
                ldsm4(bF, kBa + ((np * 16 + lr8) * ATP + kd * 16 + lk8) * 2);
                mma16(S0, aQ[kd][0], aQ[kd][1], aQ[kd][2], aQ[kd][3], bF[0], bF[1]);
                mma16(S1, aQ[kd][0], aQ[kd][1], aQ[kd][2], aQ[kd][3], bF[2], bF[3]);
            }
            // sigmoid: e = ex2(S*C1 + C0); p = 1/(1+e); ONE rcp per 4 elements
            uint32_t aP0[2], aP1[2];
            {
                float a0 = 1.f + fex2(fmaf(S0[0], C1, C0));
                float a1 = 1.f + fex2(fmaf(S0[1], C1, C0));
                float a2 = 1.f + fex2(fmaf(S0[2], C1, C0));
                float a3 = 1.f + fex2(fmaf(S0[3], C1, C0));
                float a01 = a0 * a1, a23 = a2 * a3;
                float r = frcp(a01 * a23);
                float r01 = a23 * r, r23 = a01 * r;
                __half2 h0 = __floats2half2_rn(a1 * r01, a0 * r01);
                __half2 h1 = __floats2half2_rn(a3 * r23, a2 * r23);
                aP0[0] = *(uint32_t*)&h0; aP0[1] = *(uint32_t*)&h1;
            }
            {
                float a0 = 1.f + fex2(fmaf(S1[0], C1, C0));
                float a1 = 1.f + fex2(fmaf(S1[1], C1, C0));
                float a2 = 1.f + fex2(fmaf(S1[2], C1, C0));
                float a3 = 1.f + fex2(fmaf(S1[3], C1, C0));
                float a01 = a0 * a1, a23 = a2 * a3;
                float r = frcp(a01 * a23);
                float r01 = a23 * r, r23 = a01 * r;
                __half2 h0 = __floats2half2_rn(a1 * r01, a0 * r01);
                __half2 h1 = __floats2half2_rn(a3 * r23, a2 * r23);
                aP1[0] = *(uint32_t*)&h0; aP1[1] = *(uint32_t*)&h1;
            }
            #pragma unroll
            for (int nd = 0; nd < 4; nd++) {
                uint32_t vF[4];
                ldsm4t(vF, vBa + ((np * 16 + lr) * ATP + nd * 16 + lh) * 2);
                mma16(O[nd*2],   aP0[0], aP0[1], aP1[0], aP1[1], vF[0], vF[1]);
                mma16(O[nd*2+1], aP0[0], aP0[1], aP1[0], aP1[1], vF[2], vF[3]);
            }
        }
    }

    int b = bh >> 4, h = bh & 15;
    int t1 = t0 + m0 + g, t2 = t1 + 8;
    float gq1 = g_gateq[(size_t)bh * SEQ + t1];
    float gq2 = g_gateq[(size_t)bh * SEQ + t2];
    #pragma unroll
    for (int od = 0; od < 8; od++) {
        int d = od * 8 + 2 * tg;
        *(__half2*)&g_coll[((size_t)(b * SEQ + t1) * HEADS + h) * HD + d] =
            __floats2half2_rn(O[od][0] * gq1, O[od][1] * gq1);
        *(__half2*)&g_coll[((size_t)(b * SEQ + t2) * HEADS + h) * HD + d] =
            __floats2half2_rn(O[od][2] * gq2, O[od][3] * gq2);
    }
}

// ---------------- output GEMM + bias (fp16 mma, 3-stage cp.async) ---------------
__global__ void __launch_bounds__(256) gemm_out(const float* __restrict__ bo,
                                                float* __restrict__ out) {
    extern __shared__ __align__(16) __half gsm[];
    uint32_t smem_u = s2u(gsm);

    int tid = threadIdx.x, lane = tid & 31, wid = tid >> 5;
    int g = lane >> 2, tg = lane & 3;
    int m0  = (wid & 3) * 32;
    int n0b = (wid >> 2) * 64;
    int row0 = blockIdx.y * 128, col0 = blockIdx.x * 128;

    int aRow = tid >> 1, aOff = (tid & 1) * 16;
    int bK = tid >> 3, bN = (tid & 7) * 16;
    const __half* gA = g_coll + (size_t)(row0 + aRow) * DIM + aOff;
    const __half* gB = g_Wot + (size_t)bK * DIM + col0 + bN;

    float acc[2][8][4];
    #pragma unroll
    for (int mt = 0; mt < 2; mt++)
        #pragma unroll
        for (int nt = 0; nt < 8; nt++)
            #pragma unroll
            for (int i = 0; i < 4; i++) acc[mt][nt][i] = 0.f;

    auto issue = [&](int s) {
        int k0 = s * 32, buf = s % 3;
        uint32_t da = smem_u + (buf * GQ_STG + aRow * PA + aOff) * 2;
        cpa16(da,      gA + k0);
        cpa16(da + 16, gA + k0 + 8);
        uint32_t db = smem_u + (buf * GQ_STG + 128 * PA + bK * PB + bN) * 2;
        const __half* gb = gB + (size_t)k0 * DIM;
        cpa16(db,      gb);
        cpa16(db + 16, gb + 8);
    };

    int lr = lane & 15, lh = (lane >> 4) * 8;
    issue(0); cp_commit();
    issue(1); cp_commit();
    for (int it = 0; it < 32; it++) {
        if (it < 31) cp_wait1(); else cp_wait0();
        __syncthreads();
        if (it + 2 < 32) { issue(it + 2); cp_commit(); }
        int buf = it % 3;
        uint32_t aB = smem_u + buf * GQ_STG * 2;
        uint32_t bB = aB + 128 * PA * 2;
        #pragma unroll
        for (int ks = 0; ks < 2; ks++) {
            int kk = ks * 16;
            uint32_t aF[2][4];
            #pragma unroll
            for (int mt = 0; mt < 2; mt++)
                ldsm4(aF[mt], aB + ((m0 + mt * 16 + lr) * PA + kk + lh) * 2);
            uint32_t bF[4][4];
            #pragma unroll
            for (int ntp = 0; ntp < 4; ntp++)
                ldsm4t(bF[ntp], bB + ((kk + lr) * PB + n0b + ntp * 16 + lh) * 2);
            #pragma unroll
            for (int mt = 0; mt < 2; mt++)
                #pragma unroll
                for (int ntp = 0; ntp < 4; ntp++) {
                    mma16(acc[mt][ntp*2],   aF[mt][0], aF[mt][1], aF[mt][2], aF[mt][3],
                          bF[ntp][0], bF[ntp][1]);
                    mma16(acc[mt][ntp*2+1], aF[mt][0], aF[mt][1], aF[mt][2], aF[mt][3],
                          bF[ntp][2], bF[ntp][3]);
                }
        }
    }

    #pragma unroll
    for (int mt = 0; mt < 2; mt++) {
        int r1 = row0 + m0 + mt * 16 + g;
        int r2 = r1 + 8;
        #pragma unroll
        for (int nt = 0; nt < 8; nt++) {
            int c = col0 + n0b + nt * 8 + 2 * tg;
            float2 bv = *(const float2*)(bo + c);
            *(float2*)&out[(size_t)r1 * DIM + c] =
                make_float2(acc[mt][nt][0] + bv.x, acc[mt][nt][1] + bv.y);
            *(float2*)&out[(size_t)r2 * DIM + c] =
                make_float2(acc[mt][nt][2] + bv.x, acc[mt][nt][3] + bv.y);
        }
    }
}

// ---------------- launcher ----------------
extern "C" void kernel_launch(void* const* d_in, const int* in_sizes, int n_in,
                              void* d_out, int out_size) {
    const float* x   = (const float*)d_in[0];
    const float* gq  = (const float*)d_in[4];
    const float* gk  = (const float*)d_in[5];
    const float* bo  = (const float*)d_in[7];
    const float* lnw = (const float*)d_in[8];
    const float* lnb = (const float*)d_in[9];
    float* out = (float*)d_out;

    cudaFuncSetAttribute(attn_kernel, cudaFuncAttributeMaxDynamicSharedMemorySize,
                         ATT_SMEM);
    cudaFuncSetAttribute(gemm_qkv, cudaFuncAttributeMaxDynamicSharedMemorySize,
                         GQ_SMEM);
    cudaFuncSetAttribute(gemm_out, cudaFuncAttributeMaxDynamicSharedMemorySize,
                         GQ_SMEM);

    cvtW_kernel<<<dim3(DIM * DIM / 1024, 4), 256>>>((const float*)d_in[1],
                                                    (const float*)d_in[2],
                                                    (const float*)d_in[3],
                                                    (const float*)d_in[6]);
    ln_kernel<<<MROWS, 256>>>(x, lnw, lnb);
    gemm_qkv<<<dim3(8, 32, 3), 256, GQ_SMEM>>>(gq, gk);
    scale_v_kernel<<<(BHN * SEQ * 8) / 256, 256>>>();
    attn_kernel<<<dim3(SEQ / 64, BHN), 128, ATT_SMEM>>>();
    gemm_out<<<dim3(8, 32), 256, GQ_SMEM>>>(bo, out);
}